// round 9
// baseline (speedup 1.0000x reference)
#include <cuda_runtime.h>
#include <math.h>

#define NV 20
#define NC 128
#define NT 64
#define NH 192
#define N_TL 9
#define N_LT 20
#define NDEPTH 3

// shared memory layout (floats)
#define OFF_SF   0        // 8192 : state f[64][128]
#define OFF_SY   8192     // 8192 : scratch y/z/h [64][128]
#define OFF_SG   16384    // 96
#define OFF_SRED 16480    // 16
#define OFF_SIDX 16496    // 64 ints
#define SMEM_FLOATS 16560
#define SMEM_BYTES (SMEM_FLOATS*4)

typedef unsigned long long u64;
union F2U { float2 f2; u64 u; float f[2]; };
union F4U { float4 v; u64 d[2]; float f[4]; };

struct Params {
  const float* x;
  const float* tl_table; const float* lane_table;
  const float* ch1w; const float* ch1b; const float* ch2w; const float* ch2b;
  const float* tk1w; const float* tk1b; const float* tk2w; const float* tk2b;
  const float* bn1w; const float* bn1b;
  const float* bt1w; const float* bt1b; const float* bt2w; const float* bt2b;
  const float* bn2w; const float* bn2b;
  const float* bc1w; const float* bc1b; const float* bc2w; const float* bc2b;
  const float* nw;  const float* nb;
  const float* e1w; const float* e1b; const float* e2w; const float* e2b;
  float* out; float* mask_out; float* pos_out;
};

// branchless erf-based gelu: Abramowitz&Stegun 7.1.26 (|err_erf| <= 1.5e-7)
__device__ __forceinline__ float gelu_f(float x){
  float z  = fabsf(x) * 0.70710678118654752440f;
  float t  = __fdividef(1.f, fmaf(0.3275911f, z, 1.f));
  float p  = t*(0.254829592f + t*(-0.284496736f + t*(1.421413741f +
             t*(-1.453152027f + t*1.061405429f))));
  float e  = __expf(-z*z);
  float er = copysignf(fmaf(-p, e, 1.f), x);
  return 0.5f * x * (1.f + er);
}
__device__ __forceinline__ u64 rep2(float v){
  u64 r; asm("mov.b64 %0, {%1, %1};" : "=l"(r) : "f"(v)); return r;
}
__device__ __forceinline__ void ffma2(u64& d, u64 a, u64 b){
  asm("fma.rn.f32x2 %0, %1, %2, %0;" : "+l"(d) : "l"(a), "l"(b));
}

// ---------------- token-type GEMM (weights streamed from global) -------------
// out[u][c] = sum_{k<K} A[k][c] * W[k][u];  A natural [K][128] smem, W [K][64] gmem.
// f2 halves = u-pair; j indexes the lane's c-quad:
//   acc[p][j] = (out[warp*8+2p][4*lane+j], out[warp*8+2p+1][4*lane+j])
template<int K>
__device__ __forceinline__ void tok_gemm_g(const float* A, const float* __restrict__ Wg,
                                           u64 acc[4][4], int lane, int warp){
  const float* wp = Wg + warp*8;
  const float* ap = A + 4*lane;
  #pragma unroll 4
  for (int k = 0; k < K; k++){
    F4U w0, w1, a4;
    w0.v = *reinterpret_cast<const float4*>(wp + k*64);      // uniform LDG.128
    w1.v = *reinterpret_cast<const float4*>(wp + k*64 + 4);
    a4.v = *reinterpret_cast<const float4*>(ap + k*NC);      // LDS.128 conflict-free
    u64 wp4[4] = { w0.d[0], w0.d[1], w1.d[0], w1.d[1] };
    #pragma unroll
    for (int j = 0; j < 4; j++){
      u64 a = rep2(a4.f[j]);
      #pragma unroll
      for (int p = 0; p < 4; p++) ffma2(acc[p][j], wp4[p], a);
    }
  }
}

// ---------------- channel-type GEMM (weights streamed from global) -----------
// out[t][c] = sum_{k<128} A[t][k] * W[k][c]; A rows warp-local in smem (base As),
// W [128][128] gmem, coalesced LDG.128 (lane covers c-quad 4*lane..4*lane+3).
// acc[i][0] = (c=4l, 4l+1), acc[i][1] = (4l+2, 4l+3), t = row i of As.
template<int I>
__device__ __forceinline__ void chan_gemm_g(const float* As, const float* __restrict__ Wg,
                                            u64 acc[I][2], int lane){
  const float* wl = Wg + 4*lane;
  #pragma unroll 2
  for (int c4 = 0; c4 < 32; c4++){
    float4 a4[I];
    #pragma unroll
    for (int i = 0; i < I; i++)
      a4[i] = *reinterpret_cast<const float4*>(As + i*NC + 4*c4);   // LDS.128 bcast
    #pragma unroll
    for (int r = 0; r < 4; r++){
      F4U w; w.v = *reinterpret_cast<const float4*>(wl + (4*c4 + r)*NC);  // LDG.128
      #pragma unroll
      for (int i = 0; i < I; i++){
        float av = (r==0) ? a4[i].x : (r==1) ? a4[i].y : (r==2) ? a4[i].z : a4[i].w;
        u64 a = rep2(av);
        ffma2(acc[i][0], a, w.d[0]);
        ffma2(acc[i][1], a, w.d[1]);
      }
    }
  }
}

template<int A0, int A1>
__device__ __forceinline__ void zero_acc(u64 acc[A0][A1]){
  #pragma unroll
  for (int i = 0; i < A0; i++)
    #pragma unroll
    for (int j = 0; j < A1; j++) acc[i][j] = 0ull;
}

// LN of one row (128 ch, c-quad per lane), float4 I/O, shfl reductions
__device__ __forceinline__ void ln_row(const float* srow, float* drow,
                                       const F4U& wg, const F4U& bg, int lane){
  F4U v; v.v = *reinterpret_cast<const float4*>(srow + 4*lane);
  float s = (v.f[0]+v.f[1]) + (v.f[2]+v.f[3]);
  float q = v.f[0]*v.f[0] + v.f[1]*v.f[1] + v.f[2]*v.f[2] + v.f[3]*v.f[3];
  #pragma unroll
  for (int o = 16; o > 0; o >>= 1){
    s += __shfl_xor_sync(0xffffffffu, s, o);
    q += __shfl_xor_sync(0xffffffffu, q, o);
  }
  float m   = s * (1.f/NC);
  float var = q * (1.f/NC) - m*m;
  float rs  = rsqrtf(var + 1e-5f);
  F4U o;
  #pragma unroll
  for (int j = 0; j < 4; j++) o.f[j] = (v.f[j]-m)*rs*wg.f[j] + bg.f[j];
  *reinterpret_cast<float4*>(drow + 4*lane) = o.v;
}

__global__ void __launch_bounds__(256, 2)
lane_fusion_kernel(Params P){
  extern __shared__ float smem[];
  float* sf  = smem + OFF_SF;
  float* sy  = smem + OFF_SY;
  float* sg  = smem + OFF_SG;
  float* sred= smem + OFF_SRED;
  int*   sidx= (int*)(smem + OFF_SIDX);

  const int tid  = threadIdx.x;
  const int lane = tid & 31;
  const int warp = tid >> 5;
  const int r    = blockIdx.x;
  const float* xr = P.x + (size_t)r * (NV*5);

  // ----- preprocess -----
  if (tid < NV){
    float x0 = xr[tid*5+0], x1 = xr[tid*5+1], hg = xr[tid*5+2];
    float x3 = xr[tid*5+3], x4 = xr[tid*5+4];
    float ch = cosf(hg), sh = sinf(hg);
    sg[tid*4+0] = x0; sg[tid*4+1] = x1; sg[tid*4+2] = ch; sg[tid*4+3] = sh;
    int tl = (int)x3; tl = tl < 0 ? 0 : (tl > N_TL-1 ? N_TL-1 : tl);
    int lt = (int)x4; lt = lt < 0 ? 0 : (lt > N_LT-1 ? N_LT-1 : lt);
    sidx[tid]      = tl;
    sidx[NV+tid]   = lt;
    sidx[2*NV+tid] = (x0==0.f && x1==0.f && ch==0.f && sh==0.f) ? 1 : 0;
  }
  if (tid < 5){
    float mid = xr[(NV/2)*5 + tid];
    float sc = (tid==3) ? (1.f/(N_TL-1)) : ((tid==4) ? (1.f/(N_LT-1)) : 1.f);
    P.pos_out[(size_t)r*5 + tid] = mid * sc;
  }
  __syncthreads();
  if (tid == 0){
    int mp = 1;
    for (int v = 0; v < NV; v++) mp &= sidx[2*NV+v];
    sidx[3*NV] = mp;
    P.mask_out[r] = mp ? 1.f : 0.f;
  }

  // ----- stage 1a: h1[v][c] = gelu(g @ ch1w + b) -> sy rows 0..19; 20..23 zero
  {
    int c  = tid & 127;
    int hf = tid >> 7;
    float w0 = P.ch1w[0*NC + c], w1 = P.ch1w[1*NC + c];
    float w2 = P.ch1w[2*NC + c], w3 = P.ch1w[3*NC + c];
    float b  = P.ch1b[c];
    #pragma unroll
    for (int v = hf*10; v < hf*10 + 10; v++){
      float a = b + sg[v*4+0]*w0 + sg[v*4+1]*w1 + sg[v*4+2]*w2 + sg[v*4+3]*w3;
      sy[v*NC + c] = gelu_f(a);
    }
    if (hf == 0){
      #pragma unroll
      for (int v = NV; v < 24; v++) sy[v*NC + c] = 0.f;
    }
  }
  __syncthreads();

  // ----- stage 1b: f0[v][c] = h1 @ ch2w + b + tables -> sf rows 0..19
  {
    u64 acc[3][2]; zero_acc<3,2>(acc);
    chan_gemm_g<3>(sy + warp*3*NC, P.ch2w, acc, lane);
    #pragma unroll
    for (int i = 0; i < 3; i++){
      int v = warp*3 + i;
      if (v < NV){
        int c0 = 4*lane;
        F4U b4;  b4.v  = *reinterpret_cast<const float4*>(P.ch2b + c0);
        F4U tl4; tl4.v = *reinterpret_cast<const float4*>(P.tl_table   + sidx[v]*NC    + c0);
        F4U lt4; lt4.v = *reinterpret_cast<const float4*>(P.lane_table + sidx[NV+v]*NC + c0);
        F2U a0; a0.u = acc[i][0];
        F2U a1; a1.u = acc[i][1];
        F4U o;
        o.f[0] = a0.f[0] + b4.f[0] + tl4.f[0] + lt4.f[0];
        o.f[1] = a0.f[1] + b4.f[1] + tl4.f[1] + lt4.f[1];
        o.f[2] = a1.f[0] + b4.f[2] + tl4.f[2] + lt4.f[2];
        o.f[3] = a1.f[1] + b4.f[3] + tl4.f[3] + lt4.f[3];
        *reinterpret_cast<float4*>(sf + v*NC + c0) = o.v;
      }
    }
  }
  __syncthreads();

  // ----- token expansion: 20 -> 64 -----
  {
    u64 acc[4][4]; zero_acc<4,4>(acc);
    tok_gemm_g<NV>(sf, P.tk1w, acc, lane, warp);     // reads sf rows 0..19
    #pragma unroll
    for (int p = 0; p < 4; p++){
      int u0 = warp*8 + 2*p;
      float b0 = P.tk1b[u0], b1 = P.tk1b[u0+1];
      F4U o0, o1;
      #pragma unroll
      for (int j = 0; j < 4; j++){
        F2U t; t.u = acc[p][j];
        o0.f[j] = gelu_f(t.f[0] + b0);
        o1.f[j] = gelu_f(t.f[1] + b1);
      }
      *reinterpret_cast<float4*>(sy + u0*NC     + 4*lane) = o0.v;
      *reinterpret_cast<float4*>(sy + (u0+1)*NC + 4*lane) = o1.v;
    }
    __syncthreads();
    zero_acc<4,4>(acc);
    tok_gemm_g<NT>(sy, P.tk2w, acc, lane, warp);
    #pragma unroll
    for (int p = 0; p < 4; p++){
      int t0 = warp*8 + 2*p;
      float b0 = P.tk2b[t0], b1 = P.tk2b[t0+1];
      F4U o0, o1;
      #pragma unroll
      for (int j = 0; j < 4; j++){
        F2U t; t.u = acc[p][j];
        o0.f[j] = t.f[0] + b0;
        o1.f[j] = t.f[1] + b1;
      }
      *reinterpret_cast<float4*>(sf + t0*NC     + 4*lane) = o0.v;
      *reinterpret_cast<float4*>(sf + (t0+1)*NC + 4*lane) = o1.v;
    }
  }
  __syncthreads();   // all warps done reading sy(z); sf ready

  // ----- mixer blocks -----
  for (int d = 0; d < NDEPTH; d++){
    // LN1: warp-local rows warp*8+i -> sy
    {
      F4U wg, bg;
      wg.v = *reinterpret_cast<const float4*>(P.bn1w + d*NC + 4*lane);
      bg.v = *reinterpret_cast<const float4*>(P.bn1b + d*NC + 4*lane);
      #pragma unroll
      for (int i = 0; i < 8; i++){
        int t = warp*8 + i;
        ln_row(sf + t*NC, sy + t*NC, wg, bg, lane);
      }
    }
    __syncthreads();   // A: sy(y) complete for all warps

    // token mix
    {
      u64 acc[4][4]; zero_acc<4,4>(acc);
      tok_gemm_g<NT>(sy, P.bt1w + d*NT*NT, acc, lane, warp);
      __syncthreads(); // B: all done reading y before z overwrite
      #pragma unroll
      for (int p = 0; p < 4; p++){
        int u0 = warp*8 + 2*p;
        float b0 = P.bt1b[d*NT + u0], b1 = P.bt1b[d*NT + u0+1];
        F4U o0, o1;
        #pragma unroll
        for (int j = 0; j < 4; j++){
          F2U t; t.u = acc[p][j];
          o0.f[j] = gelu_f(t.f[0] + b0);
          o1.f[j] = gelu_f(t.f[1] + b1);
        }
        *reinterpret_cast<float4*>(sy + u0*NC     + 4*lane) = o0.v;
        *reinterpret_cast<float4*>(sy + (u0+1)*NC + 4*lane) = o1.v;
      }
      __syncthreads(); // C: z complete
      zero_acc<4,4>(acc);
      tok_gemm_g<NT>(sy, P.bt2w + d*NT*NT, acc, lane, warp);
      // residual (warp-local rows)
      #pragma unroll
      for (int p = 0; p < 4; p++){
        int t0 = warp*8 + 2*p;
        float b0 = P.bt2b[d*NT + t0], b1 = P.bt2b[d*NT + t0+1];
        F4U f0; f0.v = *reinterpret_cast<const float4*>(sf + t0*NC     + 4*lane);
        F4U f1; f1.v = *reinterpret_cast<const float4*>(sf + (t0+1)*NC + 4*lane);
        #pragma unroll
        for (int j = 0; j < 4; j++){
          F2U t; t.u = acc[p][j];
          f0.f[j] += t.f[0] + b0;
          f1.f[j] += t.f[1] + b1;
        }
        *reinterpret_cast<float4*>(sf + t0*NC     + 4*lane) = f0.v;
        *reinterpret_cast<float4*>(sf + (t0+1)*NC + 4*lane) = f1.v;
      }
    }
    __syncthreads();   // D: all done reading z; sy free for LN2

    // LN2 -> sy (warp-local rows)
    {
      F4U wg, bg;
      wg.v = *reinterpret_cast<const float4*>(P.bn2w + d*NC + 4*lane);
      bg.v = *reinterpret_cast<const float4*>(P.bn2b + d*NC + 4*lane);
      #pragma unroll
      for (int i = 0; i < 8; i++){
        int t = warp*8 + i;
        ln_row(sf + t*NC, sy + t*NC, wg, bg, lane);
      }
    }
    __syncwarp();

    // channel mix C1: h = gelu(y2 @ Wc1 + b1) — warp-local rows
    {
      u64 acc[8][2]; zero_acc<8,2>(acc);
      chan_gemm_g<8>(sy + warp*8*NC, P.bc1w + d*NC*NC, acc, lane);
      F4U b4; b4.v = *reinterpret_cast<const float4*>(P.bc1b + d*NC + 4*lane);
      #pragma unroll
      for (int i = 0; i < 8; i++){
        int t = warp*8 + i;
        F2U a0; a0.u = acc[i][0];
        F2U a1; a1.u = acc[i][1];
        F4U o;
        o.f[0] = gelu_f(a0.f[0] + b4.f[0]);
        o.f[1] = gelu_f(a0.f[1] + b4.f[1]);
        o.f[2] = gelu_f(a1.f[0] + b4.f[2]);
        o.f[3] = gelu_f(a1.f[1] + b4.f[3]);
        *reinterpret_cast<float4*>(sy + t*NC + 4*lane) = o.v;
      }
    }
    __syncwarp();

    // channel mix C2: f += h @ Wc2 + b2 — warp-local rows
    {
      u64 acc[8][2]; zero_acc<8,2>(acc);
      chan_gemm_g<8>(sy + warp*8*NC, P.bc2w + d*NC*NC, acc, lane);
      F4U b4; b4.v = *reinterpret_cast<const float4*>(P.bc2b + d*NC + 4*lane);
      #pragma unroll
      for (int i = 0; i < 8; i++){
        int t = warp*8 + i;
        F2U a0; a0.u = acc[i][0];
        F2U a1; a1.u = acc[i][1];
        F4U o; o.v = *reinterpret_cast<const float4*>(sf + t*NC + 4*lane);
        o.f[0] += a0.f[0] + b4.f[0];
        o.f[1] += a0.f[1] + b4.f[1];
        o.f[2] += a1.f[0] + b4.f[2];
        o.f[3] += a1.f[1] + b4.f[3];
        *reinterpret_cast<float4*>(sf + t*NC + 4*lane) = o.v;
      }
    }
    __syncwarp();
  }
  __syncthreads();   // E: sf complete for mean

  // ----- epilogue: token mean, LN, emb MLP -----
  {
    int c  = tid & 127;
    int hf = tid >> 7;
    float ps = 0.f;
    #pragma unroll 8
    for (int t = hf*32; t < hf*32 + 32; t++) ps += sf[t*NC + c];
    sy[hf*128 + c] = ps;
  }
  __syncthreads();
  float fm = 0.f;
  if (tid < NC){
    fm = (sy[tid] + sy[128 + tid]) * (1.f/NT);
    float s = fm, q = fm*fm;
    #pragma unroll
    for (int o = 16; o > 0; o >>= 1){
      s += __shfl_xor_sync(0xffffffffu, s, o);
      q += __shfl_xor_sync(0xffffffffu, q, o);
    }
    if (lane == 0){ sred[warp] = s; sred[4+warp] = q; }
  }
  __syncthreads();
  if (tid < NC){
    float s = sred[0]+sred[1]+sred[2]+sred[3];
    float q = sred[4]+sred[5]+sred[6]+sred[7];
    float m  = s * (1.f/NC);
    float var = q * (1.f/NC) - m*m;
    float rs = rsqrtf(var + 1e-5f);
    sy[256 + tid] = (fm - m)*rs*P.nw[tid] + P.nb[tid];
  }
  __syncthreads();
  if (tid < NH){
    float a = P.e1b[tid];
    #pragma unroll 8
    for (int c = 0; c < NC; c++) a += sy[256 + c] * P.e1w[c*NH + tid];
    sy[512 + tid] = gelu_f(a);
  }
  __syncthreads();
  if (tid < NH){
    float o = P.e2b[tid];
    #pragma unroll 8
    for (int j = 0; j < NH; j++) o += sy[512 + j] * P.e2w[j*NH + tid];
    float valid = sidx[3*NV] ? 0.f : 1.f;
    P.out[(size_t)r * NH + tid] = o * valid;
  }
}

extern "C" void kernel_launch(void* const* d_in, const int* in_sizes, int n_in,
                              void* d_out, int out_size){
  (void)in_sizes; (void)n_in; (void)out_size;
  Params P;
  P.x         = (const float*)d_in[0];
  P.tl_table  = (const float*)d_in[1];
  P.lane_table= (const float*)d_in[2];
  P.ch1w = (const float*)d_in[3];  P.ch1b = (const float*)d_in[4];
  P.ch2w = (const float*)d_in[5];  P.ch2b = (const float*)d_in[6];
  P.tk1w = (const float*)d_in[7];  P.tk1b = (const float*)d_in[8];
  P.tk2w = (const float*)d_in[9];  P.tk2b = (const float*)d_in[10];
  P.bn1w = (const float*)d_in[11]; P.bn1b = (const float*)d_in[12];
  P.bt1w = (const float*)d_in[13]; P.bt1b = (const float*)d_in[14];
  P.bt2w = (const float*)d_in[15]; P.bt2b = (const float*)d_in[16];
  P.bn2w = (const float*)d_in[17]; P.bn2b = (const float*)d_in[18];
  P.bc1w = (const float*)d_in[19]; P.bc1b = (const float*)d_in[20];
  P.bc2w = (const float*)d_in[21]; P.bc2b = (const float*)d_in[22];
  P.nw   = (const float*)d_in[23]; P.nb   = (const float*)d_in[24];
  P.e1w  = (const float*)d_in[25]; P.e1b  = (const float*)d_in[26];
  P.e2w  = (const float*)d_in[27]; P.e2b  = (const float*)d_in[28];

  const int NRows = 8192;
  float* ob = (float*)d_out;
  P.out      = ob;
  P.mask_out = ob + (size_t)NRows*NH;
  P.pos_out  = ob + (size_t)NRows*NH + NRows;

  cudaFuncSetAttribute(lane_fusion_kernel,
                       cudaFuncAttributeMaxDynamicSharedMemorySize, SMEM_BYTES);
  lane_fusion_kernel<<<NRows, 256, SMEM_BYTES>>>(P);
}

// round 10
// speedup vs baseline: 1.6088x; 1.6088x over previous
#include <cuda_runtime.h>
#include <math.h>

#define NV 20
#define NC 128
#define NT 64
#define NH 192
#define N_TL 9
#define N_LT 20
#define NDEPTH 3

// shared memory layout (floats) — all natural [row][128] layouts
#define OFF_SF   0        // 8192 : state f[64][128]
#define OFF_SY   8192     // 8192 : scratch y/z/h [64][128] (h1 uses rows 0..23)
#define OFF_W0   16384    // 4096 : weight tile buffer 0
#define OFF_W1   20480    // 4096 : weight tile buffer 1
#define OFF_SG   24576    // 96
#define OFF_SRED 24672    // 16
#define OFF_SIDX 24688    // 64 ints
#define SMEM_FLOATS 24752
#define SMEM_BYTES (SMEM_FLOATS*4)

typedef unsigned long long u64;
union F2U { float2 f2; u64 u; float f[2]; };
union F4U { float4 v; u64 d[2]; float f[4]; };

struct Params {
  const float* x;
  const float* tl_table; const float* lane_table;
  const float* ch1w; const float* ch1b; const float* ch2w; const float* ch2b;
  const float* tk1w; const float* tk1b; const float* tk2w; const float* tk2b;
  const float* bn1w; const float* bn1b;
  const float* bt1w; const float* bt1b; const float* bt2w; const float* bt2b;
  const float* bn2w; const float* bn2b;
  const float* bc1w; const float* bc1b; const float* bc2w; const float* bc2b;
  const float* nw;  const float* nb;
  const float* e1w; const float* e1b; const float* e2w; const float* e2b;
  float* out; float* mask_out; float* pos_out;
};

__device__ __forceinline__ float gelu_f(float v){
  return 0.5f * v * (1.0f + erff(v * 0.70710678118654752440f));
}
__device__ __forceinline__ u64 lds_f2(const float* p){
  F2U t; t.f2 = *reinterpret_cast<const float2*>(p); return t.u;
}
__device__ __forceinline__ u64 rep2(float v){
  u64 r; asm("mov.b64 %0, {%1, %1};" : "=l"(r) : "f"(v)); return r;
}
__device__ __forceinline__ void ffma2(u64& d, u64 a, u64 b){
  asm("fma.rn.f32x2 %0, %1, %2, %0;" : "+l"(d) : "l"(a), "l"(b));
}

// ---------------- token-type GEMM ----------------
// out[u][c] = sum_{k<K} A[k][c] * W[k][u]
// f2 halves = u-pair: acc[p][j] holds (out[warp*8+2p][c], out[warp*8+2p+1][c]), c=lane+32j
// A natural [K][128] in smem; W natural [K][64] in smem (staged).
// w loaded as 2x uniform LDS.128 broadcasts (1 wavefront each) instead of 4x strided LDS.64.
template<int K>
__device__ __forceinline__ void tok_gemm(const float* A, const float* W,
                                         u64 acc[4][4], int lane, int warp){
  const float* wp = W + warp*8;
  const float* ap = A + lane;
  #pragma unroll 4
  for (int k = 0; k < K; k++){
    F4U w0, w1;
    w0.v = *reinterpret_cast<const float4*>(wp + k*64);      // LDS.128 broadcast
    w1.v = *reinterpret_cast<const float4*>(wp + k*64 + 4);  // LDS.128 broadcast
    u64 a[4];
    #pragma unroll
    for (int j = 0; j < 4; j++) a[j] = rep2(ap[k*NC + 32*j]); // LDS.32 conflict-free
    u64 wp4[4] = { w0.d[0], w0.d[1], w1.d[0], w1.d[1] };
    #pragma unroll
    for (int p = 0; p < 4; p++)
      #pragma unroll
      for (int j = 0; j < 4; j++) ffma2(acc[p][j], wp4[p], a[j]);
  }
}

// ---------------- channel-type GEMM tile (32 c's) ----------------
// out[t][j] = sum_c A[t][c] * W[c][j]
// f2 halves = j-pair: acc[i][j'] holds (out[t][2*(lane+32j')], out[t][2*(lane+32j')+1]),
// t = warp*I + i.  A natural [rows][128]; wb tile natural [32][128] (c-major rows).
template<int I>
__device__ __forceinline__ void chan_tile(const float* __restrict__ A,
                                          const float* __restrict__ wb,
                                          u64 acc[I][2], int lane, int warp, int c0){
  const float* wl = wb + 2*lane;
  #pragma unroll 2
  for (int c4 = 0; c4 < 8; c4++){
    float4 a4[I];
    #pragma unroll
    for (int i = 0; i < I; i++)
      a4[i] = *reinterpret_cast<const float4*>(A + (warp*I + i)*NC + c0 + 4*c4);  // bcast .128
    #pragma unroll
    for (int r = 0; r < 4; r++){
      int cc = 4*c4 + r;
      u64 w0 = lds_f2(wl + cc*NC);        // strided f2, conflict-free
      u64 w1 = lds_f2(wl + cc*NC + 64);
      #pragma unroll
      for (int i = 0; i < I; i++){
        float av = (r==0) ? a4[i].x : (r==1) ? a4[i].y : (r==2) ? a4[i].z : a4[i].w;
        u64 a = rep2(av);
        ffma2(acc[i][0], a, w0);
        ffma2(acc[i][1], a, w1);
      }
    }
  }
}

// full K=128 channel GEMM, ping-pong contiguous-staged 32x128 weight tiles
template<int I>
__device__ void chan_gemm_full(const float* __restrict__ A, const float* __restrict__ gw,
                               u64 acc[I][2], float* wb0, float* wb1, int tid,
                               int lane, int warp){
  const float4* g4 = reinterpret_cast<const float4*>(gw);
  float4 pre[4];
  #pragma unroll
  for (int q = 0; q < 4; q++) pre[q] = g4[tid + 256*q];
  {
    float4* s4 = reinterpret_cast<float4*>(wb0);
    #pragma unroll
    for (int q = 0; q < 4; q++) s4[tid + 256*q] = pre[q];
  }
  __syncthreads();
  #pragma unroll
  for (int t = 0; t < 4; t++){
    if (t < 3){
      #pragma unroll
      for (int q = 0; q < 4; q++) pre[q] = g4[(t+1)*1024 + tid + 256*q];
    }
    chan_tile<I>(A, (t & 1) ? wb1 : wb0, acc, lane, warp, t*32);
    if (t < 3){
      float4* s4 = reinterpret_cast<float4*>(((t+1) & 1) ? wb1 : wb0);
      #pragma unroll
      for (int q = 0; q < 4; q++) s4[tid + 256*q] = pre[q];
    }
    __syncthreads();
  }
}

// contiguous stage of n4 float4s
__device__ __forceinline__ void stage_cp(float* dst, const float* __restrict__ src,
                                         int n4, int tid){
  const float4* g4 = reinterpret_cast<const float4*>(src);
  float4* s4 = reinterpret_cast<float4*>(dst);
  for (int i = tid; i < n4; i += 256) s4[i] = g4[i];
}

template<int A0, int A1>
__device__ __forceinline__ void zero_acc(u64 acc[A0][A1]){
  #pragma unroll
  for (int i = 0; i < A0; i++)
    #pragma unroll
    for (int j = 0; j < A1; j++) acc[i][j] = 0ull;
}

__global__ void __launch_bounds__(256, 2)
lane_fusion_kernel(Params P){
  extern __shared__ float smem[];
  float* sf  = smem + OFF_SF;
  float* sy  = smem + OFF_SY;
  float* wb0 = smem + OFF_W0;
  float* wb1 = smem + OFF_W1;
  float* sg  = smem + OFF_SG;
  float* sred= smem + OFF_SRED;
  int*   sidx= (int*)(smem + OFF_SIDX);

  const int tid  = threadIdx.x;
  const int lane = tid & 31;
  const int warp = tid >> 5;
  const int r    = blockIdx.x;
  const float* xr = P.x + (size_t)r * (NV*5);

  // ----- preprocess -----
  if (tid < NV){
    float x0 = xr[tid*5+0], x1 = xr[tid*5+1], hg = xr[tid*5+2];
    float x3 = xr[tid*5+3], x4 = xr[tid*5+4];
    float ch = cosf(hg), sh = sinf(hg);
    sg[tid*4+0] = x0; sg[tid*4+1] = x1; sg[tid*4+2] = ch; sg[tid*4+3] = sh;
    int tl = (int)x3; tl = tl < 0 ? 0 : (tl > N_TL-1 ? N_TL-1 : tl);
    int lt = (int)x4; lt = lt < 0 ? 0 : (lt > N_LT-1 ? N_LT-1 : lt);
    sidx[tid]      = tl;
    sidx[NV+tid]   = lt;
    sidx[2*NV+tid] = (x0==0.f && x1==0.f && ch==0.f && sh==0.f) ? 1 : 0;
  }
  if (tid < 5){
    float mid = xr[(NV/2)*5 + tid];
    float sc = (tid==3) ? (1.f/(N_TL-1)) : ((tid==4) ? (1.f/(N_LT-1)) : 1.f);
    P.pos_out[(size_t)r*5 + tid] = mid * sc;
  }
  __syncthreads();
  if (tid == 0){
    int mp = 1;
    for (int v = 0; v < NV; v++) mp &= sidx[2*NV+v];
    sidx[3*NV] = mp;
    P.mask_out[r] = mp ? 1.f : 0.f;
  }

  // ----- stage 1a: h1[v][c] = gelu(g @ ch1w + b) -> sy rows 0..19; 20..23 zero
  {
    int c  = tid & 127;
    int hf = tid >> 7;
    float w0 = P.ch1w[0*NC + c], w1 = P.ch1w[1*NC + c];
    float w2 = P.ch1w[2*NC + c], w3 = P.ch1w[3*NC + c];
    float b  = P.ch1b[c];
    #pragma unroll
    for (int v = hf*10; v < hf*10 + 10; v++){
      float a = b + sg[v*4+0]*w0 + sg[v*4+1]*w1 + sg[v*4+2]*w2 + sg[v*4+3]*w3;
      sy[v*NC + c] = gelu_f(a);
    }
    if (hf == 0){
      #pragma unroll
      for (int v = NV; v < 24; v++) sy[v*NC + c] = 0.f;
    }
  }
  __syncthreads();

  // ----- stage 1b: f0[v][c] = h1 @ ch2w + b + tables -> sf rows 0..19
  {
    u64 acc[3][2]; zero_acc<3,2>(acc);
    chan_gemm_full<3>(sy, P.ch2w, acc, wb0, wb1, tid, lane, warp);
    #pragma unroll
    for (int i = 0; i < 3; i++){
      int v = warp*3 + i;
      if (v < NV){
        const float* tlrow = P.tl_table   + sidx[v]    * NC;
        const float* ltrow = P.lane_table + sidx[NV+v] * NC;
        #pragma unroll
        for (int jp = 0; jp < 2; jp++){
          int c = 2*(lane + 32*jp);
          F2U t; t.u = acc[i][jp];
          sf[v*NC + c]   = t.f[0] + P.ch2b[c]   + tlrow[c]   + ltrow[c];
          sf[v*NC + c+1] = t.f[1] + P.ch2b[c+1] + tlrow[c+1] + ltrow[c+1];
        }
      }
    }
  }
  __syncthreads();

  // ----- token expansion: 20 -> 64 -----
  stage_cp(wb0, P.tk1w, (NV*NT)/4, tid);
  stage_cp(wb1, P.tk2w, (NT*NT)/4, tid);
  __syncthreads();
  {
    u64 acc[4][4]; zero_acc<4,4>(acc);
    tok_gemm<NV>(sf, wb0, acc, lane, warp);
    __syncthreads();
    #pragma unroll
    for (int p = 0; p < 4; p++){
      int u0 = warp*8 + 2*p;
      float b0 = P.tk1b[u0], b1 = P.tk1b[u0+1];
      #pragma unroll
      for (int j = 0; j < 4; j++){
        int c = lane + 32*j;
        F2U t; t.u = acc[p][j];
        sy[u0*NC + c]     = gelu_f(t.f[0] + b0);
        sy[(u0+1)*NC + c] = gelu_f(t.f[1] + b1);
      }
    }
    __syncthreads();
    zero_acc<4,4>(acc);
    tok_gemm<NT>(sy, wb1, acc, lane, warp);
    #pragma unroll
    for (int p = 0; p < 4; p++){
      int t0 = warp*8 + 2*p;
      float b0 = P.tk2b[t0], b1 = P.tk2b[t0+1];
      #pragma unroll
      for (int j = 0; j < 4; j++){
        int c = lane + 32*j;
        F2U t; t.u = acc[p][j];
        sf[t0*NC + c]     = t.f[0] + b0;
        sf[(t0+1)*NC + c] = t.f[1] + b1;
      }
    }
  }
  __syncthreads();

  // ----- mixer blocks -----
  for (int d = 0; d < NDEPTH; d++){
    // LN1 -> sy (natural)
    {
      float wg[4], bg[4];
      #pragma unroll
      for (int j = 0; j < 4; j++){
        wg[j] = P.bn1w[d*NC + lane + 32*j];
        bg[j] = P.bn1b[d*NC + lane + 32*j];
      }
      for (int t = warp; t < NT; t += 8){
        float v[4]; float s = 0.f, q = 0.f;
        #pragma unroll
        for (int j = 0; j < 4; j++){
          v[j] = sf[t*NC + lane + 32*j];
          s += v[j]; q += v[j]*v[j];
        }
        #pragma unroll
        for (int o = 16; o > 0; o >>= 1){
          s += __shfl_xor_sync(0xffffffffu, s, o);
          q += __shfl_xor_sync(0xffffffffu, q, o);
        }
        float m  = s * (1.f/NC);
        float var = q * (1.f/NC) - m*m;
        float rs = rsqrtf(var + 1e-5f);
        #pragma unroll
        for (int j = 0; j < 4; j++)
          sy[t*NC + lane + 32*j] = (v[j]-m)*rs*wg[j] + bg[j];
      }
    }
    stage_cp(wb0, P.bt1w + d*NT*NT, (NT*NT)/4, tid);
    stage_cp(wb1, P.bt2w + d*NT*NT, (NT*NT)/4, tid);
    __syncthreads();

    // token mix
    {
      u64 acc[4][4]; zero_acc<4,4>(acc);
      tok_gemm<NT>(sy, wb0, acc, lane, warp);
      __syncthreads();                 // all reads of y done before z overwrite
      #pragma unroll
      for (int p = 0; p < 4; p++){
        int u0 = warp*8 + 2*p;
        float b0 = P.bt1b[d*NT + u0], b1 = P.bt1b[d*NT + u0+1];
        #pragma unroll
        for (int j = 0; j < 4; j++){
          int c = lane + 32*j;
          F2U t; t.u = acc[p][j];
          sy[u0*NC + c]     = gelu_f(t.f[0] + b0);
          sy[(u0+1)*NC + c] = gelu_f(t.f[1] + b1);
        }
      }
      __syncthreads();
      zero_acc<4,4>(acc);
      tok_gemm<NT>(sy, wb1, acc, lane, warp);
      #pragma unroll
      for (int p = 0; p < 4; p++){
        int t0 = warp*8 + 2*p;
        float b0 = P.bt2b[d*NT + t0], b1 = P.bt2b[d*NT + t0+1];
        #pragma unroll
        for (int j = 0; j < 4; j++){
          int c = lane + 32*j;
          F2U t; t.u = acc[p][j];
          sf[t0*NC + c]     += t.f[0] + b0;
          sf[(t0+1)*NC + c] += t.f[1] + b1;
        }
      }
    }
    __syncthreads();

    // LN2 -> sy (natural)
    {
      float wg[4], bg[4];
      #pragma unroll
      for (int j = 0; j < 4; j++){
        wg[j] = P.bn2w[d*NC + lane + 32*j];
        bg[j] = P.bn2b[d*NC + lane + 32*j];
      }
      for (int t = warp; t < NT; t += 8){
        float v[4]; float s = 0.f, q = 0.f;
        #pragma unroll
        for (int j = 0; j < 4; j++){
          v[j] = sf[t*NC + lane + 32*j];
          s += v[j]; q += v[j]*v[j];
        }
        #pragma unroll
        for (int o = 16; o > 0; o >>= 1){
          s += __shfl_xor_sync(0xffffffffu, s, o);
          q += __shfl_xor_sync(0xffffffffu, q, o);
        }
        float m  = s * (1.f/NC);
        float var = q * (1.f/NC) - m*m;
        float rs = rsqrtf(var + 1e-5f);
        #pragma unroll
        for (int j = 0; j < 4; j++)
          sy[t*NC + lane + 32*j] = (v[j]-m)*rs*wg[j] + bg[j];
      }
    }
    __syncthreads();

    // channel mix C1: h = gelu(y2 @ Wc1 + b1) -> sy (after full acc)
    {
      u64 acc[8][2]; zero_acc<8,2>(acc);
      chan_gemm_full<8>(sy, P.bc1w + d*NC*NC, acc, wb0, wb1, tid, lane, warp);
      #pragma unroll
      for (int i = 0; i < 8; i++){
        int t = warp*8 + i;
        #pragma unroll
        for (int jp = 0; jp < 2; jp++){
          int c = 2*(lane + 32*jp);
          F2U v; v.u = acc[i][jp];
          float2 o;
          o.x = gelu_f(v.f[0] + P.bc1b[d*NC + c]);
          o.y = gelu_f(v.f[1] + P.bc1b[d*NC + c+1]);
          *reinterpret_cast<float2*>(sy + t*NC + c) = o;
        }
      }
      __syncthreads();
      // channel mix C2: f += h @ Wc2 + b2
      zero_acc<8,2>(acc);
      chan_gemm_full<8>(sy, P.bc2w + d*NC*NC, acc, wb0, wb1, tid, lane, warp);
      #pragma unroll
      for (int i = 0; i < 8; i++){
        int t = warp*8 + i;
        #pragma unroll
        for (int jp = 0; jp < 2; jp++){
          int c = 2*(lane + 32*jp);
          F2U v; v.u = acc[i][jp];
          float2 o = *reinterpret_cast<float2*>(sf + t*NC + c);
          o.x += v.f[0] + P.bc2b[d*NC + c];
          o.y += v.f[1] + P.bc2b[d*NC + c+1];
          *reinterpret_cast<float2*>(sf + t*NC + c) = o;
        }
      }
    }
    __syncthreads();
  }

  // ----- epilogue: token mean, LN, emb MLP -----
  {
    int c  = tid & 127;
    int hf = tid >> 7;
    float ps = 0.f;
    #pragma unroll 8
    for (int t = hf*32; t < hf*32 + 32; t++) ps += sf[t*NC + c];
    sy[hf*128 + c] = ps;
  }
  __syncthreads();
  float fm = 0.f;
  if (tid < NC){
    fm = (sy[tid] + sy[128 + tid]) * (1.f/NT);
    float s = fm, q = fm*fm;
    #pragma unroll
    for (int o = 16; o > 0; o >>= 1){
      s += __shfl_xor_sync(0xffffffffu, s, o);
      q += __shfl_xor_sync(0xffffffffu, q, o);
    }
    if (lane == 0){ sred[warp] = s; sred[4+warp] = q; }
  }
  __syncthreads();
  if (tid < NC){
    float s = sred[0]+sred[1]+sred[2]+sred[3];
    float q = sred[4]+sred[5]+sred[6]+sred[7];
    float m  = s * (1.f/NC);
    float var = q * (1.f/NC) - m*m;
    float rs = rsqrtf(var + 1e-5f);
    sy[256 + tid] = (fm - m)*rs*P.nw[tid] + P.nb[tid];
  }
  __syncthreads();
  if (tid < NH){
    float a = P.e1b[tid];
    #pragma unroll 8
    for (int c = 0; c < NC; c++) a += sy[256 + c] * P.e1w[c*NH + tid];
    sy[512 + tid] = gelu_f(a);
  }
  __syncthreads();
  if (tid < NH){
    float o = P.e2b[tid];
    #pragma unroll 8
    for (int j = 0; j < NH; j++) o += sy[512 + j] * P.e2w[j*NH + tid];
    float valid = sidx[3*NV] ? 0.f : 1.f;
    P.out[(size_t)r * NH + tid] = o * valid;
  }
}

extern "C" void kernel_launch(void* const* d_in, const int* in_sizes, int n_in,
                              void* d_out, int out_size){
  (void)in_sizes; (void)n_in; (void)out_size;
  Params P;
  P.x         = (const float*)d_in[0];
  P.tl_table  = (const float*)d_in[1];
  P.lane_table= (const float*)d_in[2];
  P.ch1w = (const float*)d_in[3];  P.ch1b = (const float*)d_in[4];
  P.ch2w = (const float*)d_in[5];  P.ch2b = (const float*)d_in[6];
  P.tk1w = (const float*)d_in[7];  P.tk1b = (const float*)d_in[8];
  P.tk2w = (const float*)d_in[9];  P.tk2b = (const float*)d_in[10];
  P.bn1w = (const float*)d_in[11]; P.bn1b = (const float*)d_in[12];
  P.bt1w = (const float*)d_in[13]; P.bt1b = (const float*)d_in[14];
  P.bt2w = (const float*)d_in[15]; P.bt2b = (const float*)d_in[16];
  P.bn2w = (const float*)d_in[17]; P.bn2b = (const float*)d_in[18];
  P.bc1w = (const float*)d_in[19]; P.bc1b = (const float*)d_in[20];
  P.bc2w = (const float*)d_in[21]; P.bc2b = (const float*)d_in[22];
  P.nw   = (const float*)d_in[23]; P.nb   = (const float*)d_in[24];
  P.e1w  = (const float*)d_in[25]; P.e1b  = (const float*)d_in[26];
  P.e2w  = (const float*)d_in[27]; P.e2b  = (const float*)d_in[28];

  const int NRows = 8192;
  float* ob = (float*)d_out;
  P.out      = ob;
  P.mask_out = ob + (size_t)NRows*NH;
  P.pos_out  = ob + (size_t)NRows*NH + NRows;

  cudaFuncSetAttribute(lane_fusion_kernel,
                       cudaFuncAttributeMaxDynamicSharedMemorySize, SMEM_BYTES);
  lane_fusion_kernel<<<NRows, 256, SMEM_BYTES>>>(P);
}

// round 11
// speedup vs baseline: 1.6213x; 1.0078x over previous
#include <cuda_runtime.h>
#include <math.h>

#define NV 20
#define NC 128
#define NT 64
#define NH 192
#define N_TL 9
#define N_LT 20
#define NDEPTH 3

// shared memory layout (floats)
#define OFF_SF   0        // 8192 : state f[64][128]
#define OFF_SY   8192     // 8192 : scratch y/z/h [64][128]
#define OFF_SG   16384    // 96
#define OFF_SRED 16480    // 16
#define OFF_SIDX 16496    // 64 ints
#define SMEM_FLOATS 16560
#define SMEM_BYTES (SMEM_FLOATS*4)

typedef unsigned long long u64;
union F2U { float2 f2; u64 u; float f[2]; };
union F4U { float4 v; u64 d[2]; float f[4]; };

struct Params {
  const float* x;
  const float* tl_table; const float* lane_table;
  const float* ch1w; const float* ch1b; const float* ch2w; const float* ch2b;
  const float* tk1w; const float* tk1b; const float* tk2w; const float* tk2b;
  const float* bn1w; const float* bn1b;
  const float* bt1w; const float* bt1b; const float* bt2w; const float* bt2b;
  const float* bn2w; const float* bn2b;
  const float* bc1w; const float* bc1b; const float* bc2w; const float* bc2b;
  const float* nw;  const float* nb;
  const float* e1w; const float* e1b; const float* e2w; const float* e2b;
  float* out; float* mask_out; float* pos_out;
};

__device__ __forceinline__ float gelu_f(float v){
  return 0.5f * v * (1.0f + erff(v * 0.70710678118654752440f));
}
__device__ __forceinline__ u64 rep2(float v){
  u64 r; asm("mov.b64 %0, {%1, %1};" : "=l"(r) : "f"(v)); return r;
}
__device__ __forceinline__ void ffma2(u64& d, u64 a, u64 b){
  asm("fma.rn.f32x2 %0, %1, %2, %0;" : "+l"(d) : "l"(a), "l"(b));
}

// ---------------- token-type GEMM (weights streamed from global) -------------
// out[u][c] = sum_{k<K} A[k][c] * W[k][u];  A natural [K][128] smem, W [K][64] gmem.
// f2 halves = u-pair: acc[p][j] = (out[warp*8+2p][c], out[warp*8+2p+1][c]), c=lane+32j
template<int K>
__device__ __forceinline__ void tok_gemm_g(const float* A, const float* __restrict__ Wg,
                                           u64 acc[4][4], int lane, int warp){
  const float* wp = Wg + warp*8;
  const float* ap = A + lane;
  #pragma unroll 4
  for (int k = 0; k < K; k++){
    F4U w0, w1;
    w0.v = *reinterpret_cast<const float4*>(wp + k*64);      // uniform LDG.128
    w1.v = *reinterpret_cast<const float4*>(wp + k*64 + 4);
    u64 a[4];
    #pragma unroll
    for (int j = 0; j < 4; j++) a[j] = rep2(ap[k*NC + 32*j]); // LDS.32 conflict-free
    u64 wp4[4] = { w0.d[0], w0.d[1], w1.d[0], w1.d[1] };
    #pragma unroll
    for (int p = 0; p < 4; p++)
      #pragma unroll
      for (int j = 0; j < 4; j++) ffma2(acc[p][j], wp4[p], a[j]);
  }
}

// ---------------- channel-type GEMM (weights streamed from global) -----------
// out[t][c] = sum_{k<128} A[t][k] * W[k][c]; A rows warp-local in smem (base As),
// W [128][128] gmem, coalesced LDG.128 (lane covers c-quad 4*lane..4*lane+3).
// Weight quad hoisted per k4 and reused across all I rows IN REGISTERS
// (low live-reg peak: acc 32 + w 16 + a 4 + addr).
template<int I>
__device__ __forceinline__ void chan_gemm_g(const float* As, const float* __restrict__ Wg,
                                            u64 acc[I][2], int lane){
  const float* wl = Wg + 4*lane;
  #pragma unroll 2
  for (int k4 = 0; k4 < 32; k4++){
    F4U w[4];
    #pragma unroll
    for (int r = 0; r < 4; r++)
      w[r].v = *reinterpret_cast<const float4*>(wl + (4*k4 + r)*NC);  // LDG.128
    #pragma unroll
    for (int i = 0; i < I; i++){
      F4U a4; a4.v = *reinterpret_cast<const float4*>(As + i*NC + 4*k4);  // LDS.128 bcast
      #pragma unroll
      for (int r = 0; r < 4; r++){
        u64 a = rep2(a4.f[r]);
        ffma2(acc[i][0], a, w[r].d[0]);
        ffma2(acc[i][1], a, w[r].d[1]);
      }
    }
  }
}

template<int A0, int A1>
__device__ __forceinline__ void zero_acc(u64 acc[A0][A1]){
  #pragma unroll
  for (int i = 0; i < A0; i++)
    #pragma unroll
    for (int j = 0; j < A1; j++) acc[i][j] = 0ull;
}

// LN of one row (128 ch, 4 per lane) read from src row, written to dst row
__device__ __forceinline__ void ln_row(const float* srow, float* drow,
                                       const float wg[4], const float bg[4], int lane){
  float v[4]; float s = 0.f, q = 0.f;
  #pragma unroll
  for (int j = 0; j < 4; j++){
    v[j] = srow[lane + 32*j];
    s += v[j]; q += v[j]*v[j];
  }
  #pragma unroll
  for (int o = 16; o > 0; o >>= 1){
    s += __shfl_xor_sync(0xffffffffu, s, o);
    q += __shfl_xor_sync(0xffffffffu, q, o);
  }
  float m  = s * (1.f/NC);
  float var = q * (1.f/NC) - m*m;
  float rs = rsqrtf(var + 1e-5f);
  #pragma unroll
  for (int j = 0; j < 4; j++)
    drow[lane + 32*j] = (v[j]-m)*rs*wg[j] + bg[j];
}

__global__ void __launch_bounds__(256, 3)
lane_fusion_kernel(Params P){
  extern __shared__ float smem[];
  float* sf  = smem + OFF_SF;
  float* sy  = smem + OFF_SY;
  float* sg  = smem + OFF_SG;
  float* sred= smem + OFF_SRED;
  int*   sidx= (int*)(smem + OFF_SIDX);

  const int tid  = threadIdx.x;
  const int lane = tid & 31;
  const int warp = tid >> 5;
  const int r    = blockIdx.x;
  const float* xr = P.x + (size_t)r * (NV*5);

  // ----- preprocess -----
  if (tid < NV){
    float x0 = xr[tid*5+0], x1 = xr[tid*5+1], hg = xr[tid*5+2];
    float x3 = xr[tid*5+3], x4 = xr[tid*5+4];
    float ch = cosf(hg), sh = sinf(hg);
    sg[tid*4+0] = x0; sg[tid*4+1] = x1; sg[tid*4+2] = ch; sg[tid*4+3] = sh;
    int tl = (int)x3; tl = tl < 0 ? 0 : (tl > N_TL-1 ? N_TL-1 : tl);
    int lt = (int)x4; lt = lt < 0 ? 0 : (lt > N_LT-1 ? N_LT-1 : lt);
    sidx[tid]      = tl;
    sidx[NV+tid]   = lt;
    sidx[2*NV+tid] = (x0==0.f && x1==0.f && ch==0.f && sh==0.f) ? 1 : 0;
  }
  if (tid < 5){
    float mid = xr[(NV/2)*5 + tid];
    float sc = (tid==3) ? (1.f/(N_TL-1)) : ((tid==4) ? (1.f/(N_LT-1)) : 1.f);
    P.pos_out[(size_t)r*5 + tid] = mid * sc;
  }
  __syncthreads();
  if (tid == 0){
    int mp = 1;
    for (int v = 0; v < NV; v++) mp &= sidx[2*NV+v];
    sidx[3*NV] = mp;
    P.mask_out[r] = mp ? 1.f : 0.f;
  }

  // ----- stage 1a: h1[v][c] = gelu(g @ ch1w + b) -> sy rows 0..19; 20..23 zero
  {
    int c  = tid & 127;
    int hf = tid >> 7;
    float w0 = P.ch1w[0*NC + c], w1 = P.ch1w[1*NC + c];
    float w2 = P.ch1w[2*NC + c], w3 = P.ch1w[3*NC + c];
    float b  = P.ch1b[c];
    #pragma unroll
    for (int v = hf*10; v < hf*10 + 10; v++){
      float a = b + sg[v*4+0]*w0 + sg[v*4+1]*w1 + sg[v*4+2]*w2 + sg[v*4+3]*w3;
      sy[v*NC + c] = gelu_f(a);
    }
    if (hf == 0){
      #pragma unroll
      for (int v = NV; v < 24; v++) sy[v*NC + c] = 0.f;
    }
  }
  __syncthreads();

  // ----- stage 1b: f0[v][c] = h1 @ ch2w + b + tables -> sf rows 0..19
  {
    u64 acc[3][2]; zero_acc<3,2>(acc);
    chan_gemm_g<3>(sy + warp*3*NC, P.ch2w, acc, lane);
    #pragma unroll
    for (int i = 0; i < 3; i++){
      int v = warp*3 + i;
      if (v < NV){
        int c0 = 4*lane;
        F4U b4;  b4.v  = *reinterpret_cast<const float4*>(P.ch2b + c0);
        F4U tl4; tl4.v = *reinterpret_cast<const float4*>(P.tl_table   + sidx[v]*NC    + c0);
        F4U lt4; lt4.v = *reinterpret_cast<const float4*>(P.lane_table + sidx[NV+v]*NC + c0);
        F2U a0; a0.u = acc[i][0];
        F2U a1; a1.u = acc[i][1];
        F4U o;
        o.f[0] = a0.f[0] + b4.f[0] + tl4.f[0] + lt4.f[0];
        o.f[1] = a0.f[1] + b4.f[1] + tl4.f[1] + lt4.f[1];
        o.f[2] = a1.f[0] + b4.f[2] + tl4.f[2] + lt4.f[2];
        o.f[3] = a1.f[1] + b4.f[3] + tl4.f[3] + lt4.f[3];
        *reinterpret_cast<float4*>(sf + v*NC + c0) = o.v;
      }
    }
  }
  __syncthreads();

  // ----- token expansion: 20 -> 64 -----
  {
    u64 acc[4][4]; zero_acc<4,4>(acc);
    tok_gemm_g<NV>(sf, P.tk1w, acc, lane, warp);     // reads sf rows 0..19
    #pragma unroll
    for (int p = 0; p < 4; p++){
      int u0 = warp*8 + 2*p;
      float b0 = P.tk1b[u0], b1 = P.tk1b[u0+1];
      #pragma unroll
      for (int j = 0; j < 4; j++){
        int c = lane + 32*j;
        F2U t; t.u = acc[p][j];
        sy[u0*NC + c]     = gelu_f(t.f[0] + b0);
        sy[(u0+1)*NC + c] = gelu_f(t.f[1] + b1);
      }
    }
    __syncthreads();
    zero_acc<4,4>(acc);
    tok_gemm_g<NT>(sy, P.tk2w, acc, lane, warp);
    #pragma unroll
    for (int p = 0; p < 4; p++){
      int t0 = warp*8 + 2*p;
      float b0 = P.tk2b[t0], b1 = P.tk2b[t0+1];
      #pragma unroll
      for (int j = 0; j < 4; j++){
        int c = lane + 32*j;
        F2U t; t.u = acc[p][j];
        sf[t0*NC + c]     = t.f[0] + b0;
        sf[(t0+1)*NC + c] = t.f[1] + b1;
      }
    }
  }
  __syncthreads();   // all warps done reading sy(z); sf ready

  // ----- mixer blocks -----
  for (int d = 0; d < NDEPTH; d++){
    // LN1: warp-local rows warp*8+i -> sy
    {
      float wg[4], bg[4];
      #pragma unroll
      for (int j = 0; j < 4; j++){
        wg[j] = P.bn1w[d*NC + lane + 32*j];
        bg[j] = P.bn1b[d*NC + lane + 32*j];
      }
      #pragma unroll
      for (int i = 0; i < 8; i++){
        int t = warp*8 + i;
        ln_row(sf + t*NC, sy + t*NC, wg, bg, lane);
      }
    }
    __syncthreads();   // A: sy(y) complete for all warps

    // token mix
    {
      u64 acc[4][4]; zero_acc<4,4>(acc);
      tok_gemm_g<NT>(sy, P.bt1w + d*NT*NT, acc, lane, warp);
      __syncthreads(); // B: all done reading y before z overwrite
      #pragma unroll
      for (int p = 0; p < 4; p++){
        int u0 = warp*8 + 2*p;
        float b0 = P.bt1b[d*NT + u0], b1 = P.bt1b[d*NT + u0+1];
        #pragma unroll
        for (int j = 0; j < 4; j++){
          int c = lane + 32*j;
          F2U t; t.u = acc[p][j];
          sy[u0*NC + c]     = gelu_f(t.f[0] + b0);
          sy[(u0+1)*NC + c] = gelu_f(t.f[1] + b1);
        }
      }
      __syncthreads(); // C: z complete
      zero_acc<4,4>(acc);
      tok_gemm_g<NT>(sy, P.bt2w + d*NT*NT, acc, lane, warp);
      // residual (warp-local rows)
      #pragma unroll
      for (int p = 0; p < 4; p++){
        int t0 = warp*8 + 2*p;
        float b0 = P.bt2b[d*NT + t0], b1 = P.bt2b[d*NT + t0+1];
        #pragma unroll
        for (int j = 0; j < 4; j++){
          int c = lane + 32*j;
          F2U t; t.u = acc[p][j];
          sf[t0*NC + c]     += t.f[0] + b0;
          sf[(t0+1)*NC + c] += t.f[1] + b1;
        }
      }
    }
    __syncthreads();   // D: all done reading z; sy free for LN2

    // LN2 -> sy (warp-local rows)
    {
      float wg[4], bg[4];
      #pragma unroll
      for (int j = 0; j < 4; j++){
        wg[j] = P.bn2w[d*NC + lane + 32*j];
        bg[j] = P.bn2b[d*NC + lane + 32*j];
      }
      #pragma unroll
      for (int i = 0; i < 8; i++){
        int t = warp*8 + i;
        ln_row(sf + t*NC, sy + t*NC, wg, bg, lane);
      }
    }
    __syncwarp();

    // channel mix C1: h = gelu(y2 @ Wc1 + b1) — warp-local rows, weights via LDG
    {
      u64 acc[8][2]; zero_acc<8,2>(acc);
      chan_gemm_g<8>(sy + warp*8*NC, P.bc1w + d*NC*NC, acc, lane);
      F4U b4; b4.v = *reinterpret_cast<const float4*>(P.bc1b + d*NC + 4*lane);
      #pragma unroll
      for (int i = 0; i < 8; i++){
        int t = warp*8 + i;
        F2U a0; a0.u = acc[i][0];
        F2U a1; a1.u = acc[i][1];
        F4U o;
        o.f[0] = gelu_f(a0.f[0] + b4.f[0]);
        o.f[1] = gelu_f(a0.f[1] + b4.f[1]);
        o.f[2] = gelu_f(a1.f[0] + b4.f[2]);
        o.f[3] = gelu_f(a1.f[1] + b4.f[3]);
        *reinterpret_cast<float4*>(sy + t*NC + 4*lane) = o.v;
      }
    }
    __syncwarp();

    // channel mix C2: f += h @ Wc2 + b2 — warp-local rows
    {
      u64 acc[8][2]; zero_acc<8,2>(acc);
      chan_gemm_g<8>(sy + warp*8*NC, P.bc2w + d*NC*NC, acc, lane);
      F4U b4; b4.v = *reinterpret_cast<const float4*>(P.bc2b + d*NC + 4*lane);
      #pragma unroll
      for (int i = 0; i < 8; i++){
        int t = warp*8 + i;
        F2U a0; a0.u = acc[i][0];
        F2U a1; a1.u = acc[i][1];
        F4U o; o.v = *reinterpret_cast<const float4*>(sf + t*NC + 4*lane);
        o.f[0] += a0.f[0] + b4.f[0];
        o.f[1] += a0.f[1] + b4.f[1];
        o.f[2] += a1.f[0] + b4.f[2];
        o.f[3] += a1.f[1] + b4.f[3];
        *reinterpret_cast<float4*>(sf + t*NC + 4*lane) = o.v;
      }
    }
    __syncwarp();
    // next LN1 reads sf warp-local rows; no block sync needed inside loop
  }
  __syncthreads();   // E: sf complete for mean

  // ----- epilogue: token mean, LN, emb MLP -----
  {
    int c  = tid & 127;
    int hf = tid >> 7;
    float ps = 0.f;
    #pragma unroll 8
    for (int t = hf*32; t < hf*32 + 32; t++) ps += sf[t*NC + c];
    sy[hf*128 + c] = ps;
  }
  __syncthreads();
  float fm = 0.f;
  if (tid < NC){
    fm = (sy[tid] + sy[128 + tid]) * (1.f/NT);
    float s = fm, q = fm*fm;
    #pragma unroll
    for (int o = 16; o > 0; o >>= 1){
      s += __shfl_xor_sync(0xffffffffu, s, o);
      q += __shfl_xor_sync(0xffffffffu, q, o);
    }
    if (lane == 0){ sred[warp] = s; sred[4+warp] = q; }
  }
  __syncthreads();
  if (tid < NC){
    float s = sred[0]+sred[1]+sred[2]+sred[3];
    float q = sred[4]+sred[5]+sred[6]+sred[7];
    float m  = s * (1.f/NC);
    float var = q * (1.f/NC) - m*m;
    float rs = rsqrtf(var + 1e-5f);
    sy[256 + tid] = (fm - m)*rs*P.nw[tid] + P.nb[tid];
  }
  __syncthreads();
  if (tid < NH){
    float a = P.e1b[tid];
    #pragma unroll 8
    for (int c = 0; c < NC; c++) a += sy[256 + c] * P.e1w[c*NH + tid];
    sy[512 + tid] = gelu_f(a);
  }
  __syncthreads();
  if (tid < NH){
    float o = P.e2b[tid];
    #pragma unroll 8
    for (int j = 0; j < NH; j++) o += sy[512 + j] * P.e2w[j*NH + tid];
    float valid = sidx[3*NV] ? 0.f : 1.f;
    P.out[(size_t)r * NH + tid] = o * valid;
  }
}

extern "C" void kernel_launch(void* const* d_in, const int* in_sizes, int n_in,
                              void* d_out, int out_size){
  (void)in_sizes; (void)n_in; (void)out_size;
  Params P;
  P.x         = (const float*)d_in[0];
  P.tl_table  = (const float*)d_in[1];
  P.lane_table= (const float*)d_in[2];
  P.ch1w = (const float*)d_in[3];  P.ch1b = (const float*)d_in[4];
  P.ch2w = (const float*)d_in[5];  P.ch2b = (const float*)d_in[6];
  P.tk1w = (const float*)d_in[7];  P.tk1b = (const float*)d_in[8];
  P.tk2w = (const float*)d_in[9];  P.tk2b = (const float*)d_in[10];
  P.bn1w = (const float*)d_in[11]; P.bn1b = (const float*)d_in[12];
  P.bt1w = (const float*)d_in[13]; P.bt1b = (const float*)d_in[14];
  P.bt2w = (const float*)d_in[15]; P.bt2b = (const float*)d_in[16];
  P.bn2w = (const float*)d_in[17]; P.bn2b = (const float*)d_in[18];
  P.bc1w = (const float*)d_in[19]; P.bc1b = (const float*)d_in[20];
  P.bc2w = (const float*)d_in[21]; P.bc2b = (const float*)d_in[22];
  P.nw   = (const float*)d_in[23]; P.nb   = (const float*)d_in[24];
  P.e1w  = (const float*)d_in[25]; P.e1b  = (const float*)d_in[26];
  P.e2w  = (const float*)d_in[27]; P.e2b  = (const float*)d_in[28];

  const int NRows = 8192;
  float* ob = (float*)d_out;
  P.out      = ob;
  P.mask_out = ob + (size_t)NRows*NH;
  P.pos_out  = ob + (size_t)NRows*NH + NRows;

  cudaFuncSetAttribute(lane_fusion_kernel,
                       cudaFuncAttributeMaxDynamicSharedMemorySize, SMEM_BYTES);
  lane_fusion_kernel<<<NRows, 256, SMEM_BYTES>>>(P);
}

// round 12
// speedup vs baseline: 1.6448x; 1.0145x over previous
#include <cuda_runtime.h>
#include <math.h>

#define NV 20
#define NC 128
#define NT 64
#define NH 192
#define N_TL 9
#define N_LT 20
#define NDEPTH 3

// shared memory layout (floats)
#define OFF_SF   0        // 8192 : state f[64][128]
#define OFF_SY   8192     // 8192 : scratch y/z/h [64][128]
#define OFF_W0   16384    // 4096 : token weight buffer 0 (tk1w / bt1w)
#define OFF_W1   20480    // 4096 : token weight buffer 1 (tk2w / bt2w)
#define OFF_SG   24576    // 96
#define OFF_SRED 24672    // 16
#define OFF_SIDX 24688    // 64 ints
#define SMEM_FLOATS 24752
#define SMEM_BYTES (SMEM_FLOATS*4)

typedef unsigned long long u64;
union F2U { float2 f2; u64 u; float f[2]; };
union F4U { float4 v; u64 d[2]; float f[4]; };

struct Params {
  const float* x;
  const float* tl_table; const float* lane_table;
  const float* ch1w; const float* ch1b; const float* ch2w; const float* ch2b;
  const float* tk1w; const float* tk1b; const float* tk2w; const float* tk2b;
  const float* bn1w; const float* bn1b;
  const float* bt1w; const float* bt1b; const float* bt2w; const float* bt2b;
  const float* bn2w; const float* bn2b;
  const float* bc1w; const float* bc1b; const float* bc2w; const float* bc2b;
  const float* nw;  const float* nb;
  const float* e1w; const float* e1b; const float* e2w; const float* e2b;
  float* out; float* mask_out; float* pos_out;
};

__device__ __forceinline__ float gelu_f(float v){
  return 0.5f * v * (1.0f + erff(v * 0.70710678118654752440f));
}
__device__ __forceinline__ u64 rep2(float v){
  u64 r; asm("mov.b64 %0, {%1, %1};" : "=l"(r) : "f"(v)); return r;
}
__device__ __forceinline__ void ffma2(u64& d, u64 a, u64 b){
  asm("fma.rn.f32x2 %0, %1, %2, %0;" : "+l"(d) : "l"(a), "l"(b));
}

// ---------------- token-type GEMM (weights in smem) --------------------------
// out[u][c] = sum_{k<K} A[k][c] * W[k][u];  A natural [K][128] smem, W [K][64] smem.
// f2 halves = u-pair: acc[p][j] = (out[warp*8+2p][c], out[warp*8+2p+1][c]), c=lane+32j
// w loaded as 2x uniform LDS.128 broadcasts; a as LDS.32 conflict-free.
template<int K>
__device__ __forceinline__ void tok_gemm(const float* A, const float* Ws,
                                         u64 acc[4][4], int lane, int warp){
  const float* wp = Ws + warp*8;
  const float* ap = A + lane;
  #pragma unroll 4
  for (int k = 0; k < K; k++){
    F4U w0, w1;
    w0.v = *reinterpret_cast<const float4*>(wp + k*64);      // LDS.128 broadcast
    w1.v = *reinterpret_cast<const float4*>(wp + k*64 + 4);  // LDS.128 broadcast
    u64 a[4];
    #pragma unroll
    for (int j = 0; j < 4; j++) a[j] = rep2(ap[k*NC + 32*j]); // LDS.32
    u64 wp4[4] = { w0.d[0], w0.d[1], w1.d[0], w1.d[1] };
    #pragma unroll
    for (int p = 0; p < 4; p++)
      #pragma unroll
      for (int j = 0; j < 4; j++) ffma2(acc[p][j], wp4[p], a[j]);
  }
}

// ---------------- channel-type GEMM (weights streamed, SW-pipelined) ---------
// out[t][c] = sum_{k<128} A[t][k] * W[k][c]; A rows warp-local in smem (base As),
// W [128][128] gmem, coalesced LDG.128; weight quad for k4+1 prefetched into
// registers while k4's 8 rows compute (covers L2 latency).
template<int I>
__device__ __forceinline__ void chan_gemm_g(const float* As, const float* __restrict__ Wg,
                                            u64 acc[I][2], int lane){
  const float* wl = Wg + 4*lane;
  F4U w[4];
  #pragma unroll
  for (int r = 0; r < 4; r++)
    w[r].v = *reinterpret_cast<const float4*>(wl + r*NC);
  #pragma unroll 2
  for (int k4 = 0; k4 < 32; k4++){
    F4U wn[4];
    if (k4 < 31){
      #pragma unroll
      for (int r = 0; r < 4; r++)
        wn[r].v = *reinterpret_cast<const float4*>(wl + (4*(k4+1) + r)*NC);  // prefetch
    }
    #pragma unroll
    for (int i = 0; i < I; i++){
      F4U a4; a4.v = *reinterpret_cast<const float4*>(As + i*NC + 4*k4);  // LDS.128 bcast
      #pragma unroll
      for (int r = 0; r < 4; r++){
        u64 a = rep2(a4.f[r]);
        ffma2(acc[i][0], a, w[r].d[0]);
        ffma2(acc[i][1], a, w[r].d[1]);
      }
    }
    if (k4 < 31){
      #pragma unroll
      for (int r = 0; r < 4; r++) w[r] = wn[r];
    }
  }
}

// contiguous stage of n4 float4s
__device__ __forceinline__ void stage_cp(float* dst, const float* __restrict__ src,
                                         int n4, int tid){
  const float4* g4 = reinterpret_cast<const float4*>(src);
  float4* s4 = reinterpret_cast<float4*>(dst);
  for (int i = tid; i < n4; i += 256) s4[i] = g4[i];
}

template<int A0, int A1>
__device__ __forceinline__ void zero_acc(u64 acc[A0][A1]){
  #pragma unroll
  for (int i = 0; i < A0; i++)
    #pragma unroll
    for (int j = 0; j < A1; j++) acc[i][j] = 0ull;
}

// LN of one row (128 ch, 4 per lane) read from src row, written to dst row
__device__ __forceinline__ void ln_row(const float* srow, float* drow,
                                       const float wg[4], const float bg[4], int lane){
  float v[4]; float s = 0.f, q = 0.f;
  #pragma unroll
  for (int j = 0; j < 4; j++){
    v[j] = srow[lane + 32*j];
    s += v[j]; q += v[j]*v[j];
  }
  #pragma unroll
  for (int o = 16; o > 0; o >>= 1){
    s += __shfl_xor_sync(0xffffffffu, s, o);
    q += __shfl_xor_sync(0xffffffffu, q, o);
  }
  float m  = s * (1.f/NC);
  float var = q * (1.f/NC) - m*m;
  float rs = rsqrtf(var + 1e-5f);
  #pragma unroll
  for (int j = 0; j < 4; j++)
    drow[lane + 32*j] = (v[j]-m)*rs*wg[j] + bg[j];
}

__global__ void __launch_bounds__(256, 2)
lane_fusion_kernel(Params P){
  extern __shared__ float smem[];
  float* sf  = smem + OFF_SF;
  float* sy  = smem + OFF_SY;
  float* wb0 = smem + OFF_W0;
  float* wb1 = smem + OFF_W1;
  float* sg  = smem + OFF_SG;
  float* sred= smem + OFF_SRED;
  int*   sidx= (int*)(smem + OFF_SIDX);

  const int tid  = threadIdx.x;
  const int lane = tid & 31;
  const int warp = tid >> 5;
  const int r    = blockIdx.x;
  const float* xr = P.x + (size_t)r * (NV*5);

  // ----- preprocess -----
  if (tid < NV){
    float x0 = xr[tid*5+0], x1 = xr[tid*5+1], hg = xr[tid*5+2];
    float x3 = xr[tid*5+3], x4 = xr[tid*5+4];
    float ch = cosf(hg), sh = sinf(hg);
    sg[tid*4+0] = x0; sg[tid*4+1] = x1; sg[tid*4+2] = ch; sg[tid*4+3] = sh;
    int tl = (int)x3; tl = tl < 0 ? 0 : (tl > N_TL-1 ? N_TL-1 : tl);
    int lt = (int)x4; lt = lt < 0 ? 0 : (lt > N_LT-1 ? N_LT-1 : lt);
    sidx[tid]      = tl;
    sidx[NV+tid]   = lt;
    sidx[2*NV+tid] = (x0==0.f && x1==0.f && ch==0.f && sh==0.f) ? 1 : 0;
  }
  if (tid < 5){
    float mid = xr[(NV/2)*5 + tid];
    float sc = (tid==3) ? (1.f/(N_TL-1)) : ((tid==4) ? (1.f/(N_LT-1)) : 1.f);
    P.pos_out[(size_t)r*5 + tid] = mid * sc;
  }
  __syncthreads();
  if (tid == 0){
    int mp = 1;
    for (int v = 0; v < NV; v++) mp &= sidx[2*NV+v];
    sidx[3*NV] = mp;
    P.mask_out[r] = mp ? 1.f : 0.f;
  }

  // ----- stage 1a: h1[v][c] = gelu(g @ ch1w + b) -> sy rows 0..19; 20..23 zero
  // also stage token-expansion weights into smem (read after next-next sync)
  {
    int c  = tid & 127;
    int hf = tid >> 7;
    float w0 = P.ch1w[0*NC + c], w1 = P.ch1w[1*NC + c];
    float w2 = P.ch1w[2*NC + c], w3 = P.ch1w[3*NC + c];
    float b  = P.ch1b[c];
    #pragma unroll
    for (int v = hf*10; v < hf*10 + 10; v++){
      float a = b + sg[v*4+0]*w0 + sg[v*4+1]*w1 + sg[v*4+2]*w2 + sg[v*4+3]*w3;
      sy[v*NC + c] = gelu_f(a);
    }
    if (hf == 0){
      #pragma unroll
      for (int v = NV; v < 24; v++) sy[v*NC + c] = 0.f;
    }
    stage_cp(wb0, P.tk1w, (NV*NT)/4, tid);
    stage_cp(wb1, P.tk2w, (NT*NT)/4, tid);
  }
  __syncthreads();

  // ----- stage 1b: f0[v][c] = h1 @ ch2w + b + tables -> sf rows 0..19
  {
    u64 acc[3][2]; zero_acc<3,2>(acc);
    chan_gemm_g<3>(sy + warp*3*NC, P.ch2w, acc, lane);
    #pragma unroll
    for (int i = 0; i < 3; i++){
      int v = warp*3 + i;
      if (v < NV){
        int c0 = 4*lane;
        F4U b4;  b4.v  = *reinterpret_cast<const float4*>(P.ch2b + c0);
        F4U tl4; tl4.v = *reinterpret_cast<const float4*>(P.tl_table   + sidx[v]*NC    + c0);
        F4U lt4; lt4.v = *reinterpret_cast<const float4*>(P.lane_table + sidx[NV+v]*NC + c0);
        F2U a0; a0.u = acc[i][0];
        F2U a1; a1.u = acc[i][1];
        F4U o;
        o.f[0] = a0.f[0] + b4.f[0] + tl4.f[0] + lt4.f[0];
        o.f[1] = a0.f[1] + b4.f[1] + tl4.f[1] + lt4.f[1];
        o.f[2] = a1.f[0] + b4.f[2] + tl4.f[2] + lt4.f[2];
        o.f[3] = a1.f[1] + b4.f[3] + tl4.f[3] + lt4.f[3];
        *reinterpret_cast<float4*>(sf + v*NC + c0) = o.v;
      }
    }
  }
  __syncthreads();

  // ----- token expansion: 20 -> 64 (weights from smem) -----
  {
    u64 acc[4][4]; zero_acc<4,4>(acc);
    tok_gemm<NV>(sf, wb0, acc, lane, warp);     // reads sf rows 0..19
    #pragma unroll
    for (int p = 0; p < 4; p++){
      int u0 = warp*8 + 2*p;
      float b0 = P.tk1b[u0], b1 = P.tk1b[u0+1];
      #pragma unroll
      for (int j = 0; j < 4; j++){
        int c = lane + 32*j;
        F2U t; t.u = acc[p][j];
        sy[u0*NC + c]     = gelu_f(t.f[0] + b0);
        sy[(u0+1)*NC + c] = gelu_f(t.f[1] + b1);
      }
    }
    __syncthreads();
    zero_acc<4,4>(acc);
    tok_gemm<NT>(sy, wb1, acc, lane, warp);
    #pragma unroll
    for (int p = 0; p < 4; p++){
      int t0 = warp*8 + 2*p;
      float b0 = P.tk2b[t0], b1 = P.tk2b[t0+1];
      #pragma unroll
      for (int j = 0; j < 4; j++){
        int c = lane + 32*j;
        F2U t; t.u = acc[p][j];
        sf[t0*NC + c]     = t.f[0] + b0;
        sf[(t0+1)*NC + c] = t.f[1] + b1;
      }
    }
  }
  __syncthreads();   // all warps done reading sy(z)+wb1; sf ready

  // ----- mixer blocks -----
  for (int d = 0; d < NDEPTH; d++){
    // LN1: warp-local rows warp*8+i -> sy ; stage this depth's token weights
    {
      float wg[4], bg[4];
      #pragma unroll
      for (int j = 0; j < 4; j++){
        wg[j] = P.bn1w[d*NC + lane + 32*j];
        bg[j] = P.bn1b[d*NC + lane + 32*j];
      }
      #pragma unroll
      for (int i = 0; i < 8; i++){
        int t = warp*8 + i;
        ln_row(sf + t*NC, sy + t*NC, wg, bg, lane);
      }
      stage_cp(wb0, P.bt1w + d*NT*NT, (NT*NT)/4, tid);
      stage_cp(wb1, P.bt2w + d*NT*NT, (NT*NT)/4, tid);
    }
    __syncthreads();   // A: sy(y) + wb complete for all warps

    // token mix (weights from smem)
    {
      u64 acc[4][4]; zero_acc<4,4>(acc);
      tok_gemm<NT>(sy, wb0, acc, lane, warp);
      __syncthreads(); // B: all done reading y before z overwrite
      #pragma unroll
      for (int p = 0; p < 4; p++){
        int u0 = warp*8 + 2*p;
        float b0 = P.bt1b[d*NT + u0], b1 = P.bt1b[d*NT + u0+1];
        #pragma unroll
        for (int j = 0; j < 4; j++){
          int c = lane + 32*j;
          F2U t; t.u = acc[p][j];
          sy[u0*NC + c]     = gelu_f(t.f[0] + b0);
          sy[(u0+1)*NC + c] = gelu_f(t.f[1] + b1);
        }
      }
      __syncthreads(); // C: z complete
      zero_acc<4,4>(acc);
      tok_gemm<NT>(sy, wb1, acc, lane, warp);
      // residual (warp-local rows)
      #pragma unroll
      for (int p = 0; p < 4; p++){
        int t0 = warp*8 + 2*p;
        float b0 = P.bt2b[d*NT + t0], b1 = P.bt2b[d*NT + t0+1];
        #pragma unroll
        for (int j = 0; j < 4; j++){
          int c = lane + 32*j;
          F2U t; t.u = acc[p][j];
          sf[t0*NC + c]     += t.f[0] + b0;
          sf[(t0+1)*NC + c] += t.f[1] + b1;
        }
      }
    }
    __syncthreads();   // D: all done reading z+wb1; sy free for LN2

    // LN2 -> sy (warp-local rows)
    {
      float wg[4], bg[4];
      #pragma unroll
      for (int j = 0; j < 4; j++){
        wg[j] = P.bn2w[d*NC + lane + 32*j];
        bg[j] = P.bn2b[d*NC + lane + 32*j];
      }
      #pragma unroll
      for (int i = 0; i < 8; i++){
        int t = warp*8 + i;
        ln_row(sf + t*NC, sy + t*NC, wg, bg, lane);
      }
    }
    __syncwarp();

    // channel mix C1: h = gelu(y2 @ Wc1 + b1) — warp-local rows, pipelined LDG
    {
      u64 acc[8][2]; zero_acc<8,2>(acc);
      chan_gemm_g<8>(sy + warp*8*NC, P.bc1w + d*NC*NC, acc, lane);
      F4U b4; b4.v = *reinterpret_cast<const float4*>(P.bc1b + d*NC + 4*lane);
      #pragma unroll
      for (int i = 0; i < 8; i++){
        int t = warp*8 + i;
        F2U a0; a0.u = acc[i][0];
        F2U a1; a1.u = acc[i][1];
        F4U o;
        o.f[0] = gelu_f(a0.f[0] + b4.f[0]);
        o.f[1] = gelu_f(a0.f[1] + b4.f[1]);
        o.f[2] = gelu_f(a1.f[0] + b4.f[2]);
        o.f[3] = gelu_f(a1.f[1] + b4.f[3]);
        *reinterpret_cast<float4*>(sy + t*NC + 4*lane) = o.v;
      }
    }
    __syncwarp();

    // channel mix C2: f += h @ Wc2 + b2 — warp-local rows
    {
      u64 acc[8][2]; zero_acc<8,2>(acc);
      chan_gemm_g<8>(sy + warp*8*NC, P.bc2w + d*NC*NC, acc, lane);
      F4U b4; b4.v = *reinterpret_cast<const float4*>(P.bc2b + d*NC + 4*lane);
      #pragma unroll
      for (int i = 0; i < 8; i++){
        int t = warp*8 + i;
        F2U a0; a0.u = acc[i][0];
        F2U a1; a1.u = acc[i][1];
        F4U o; o.v = *reinterpret_cast<const float4*>(sf + t*NC + 4*lane);
        o.f[0] += a0.f[0] + b4.f[0];
        o.f[1] += a0.f[1] + b4.f[1];
        o.f[2] += a1.f[0] + b4.f[2];
        o.f[3] += a1.f[1] + b4.f[3];
        *reinterpret_cast<float4*>(sf + t*NC + 4*lane) = o.v;
      }
    }
    __syncwarp();
    // next LN1 reads sf warp-local rows; D-sync of next iteration orders wb reuse
  }
  __syncthreads();   // E: sf complete for mean

  // ----- epilogue: token mean, LN, emb MLP -----
  {
    int c  = tid & 127;
    int hf = tid >> 7;
    float ps = 0.f;
    #pragma unroll 8
    for (int t = hf*32; t < hf*32 + 32; t++) ps += sf[t*NC + c];
    sy[hf*128 + c] = ps;
  }
  __syncthreads();
  float fm = 0.f;
  if (tid < NC){
    fm = (sy[tid] + sy[128 + tid]) * (1.f/NT);
    float s = fm, q = fm*fm;
    #pragma unroll
    for (int o = 16; o > 0; o >>= 1){
      s += __shfl_xor_sync(0xffffffffu, s, o);
      q += __shfl_xor_sync(0xffffffffu, q, o);
    }
    if (lane == 0){ sred[warp] = s; sred[4+warp] = q; }
  }
  __syncthreads();
  if (tid < NC){
    float s = sred[0]+sred[1]+sred[2]+sred[3];
    float q = sred[4]+sred[5]+sred[6]+sred[7];
    float m  = s * (1.f/NC);
    float var = q * (1.f/NC) - m*m;
    float rs = rsqrtf(var + 1e-5f);
    sy[256 + tid] = (fm - m)*rs*P.nw[tid] + P.nb[tid];
  }
  __syncthreads();
  if (tid < NH){
    float a = P.e1b[tid];
    #pragma unroll 8
    for (int c = 0; c < NC; c++) a += sy[256 + c] * P.e1w[c*NH + tid];
    sy[512 + tid] = gelu_f(a);
  }
  __syncthreads();
  if (tid < NH){
    float o = P.e2b[tid];
    #pragma unroll 8
    for (int j = 0; j < NH; j++) o += sy[512 + j] * P.e2w[j*NH + tid];
    float valid = sidx[3*NV] ? 0.f : 1.f;
    P.out[(size_t)r * NH + tid] = o * valid;
  }
}

extern "C" void kernel_launch(void* const* d_in, const int* in_sizes, int n_in,
                              void* d_out, int out_size){
  (void)in_sizes; (void)n_in; (void)out_size;
  Params P;
  P.x         = (const float*)d_in[0];
  P.tl_table  = (const float*)d_in[1];
  P.lane_table= (const float*)d_in[2];
  P.ch1w = (const float*)d_in[3];  P.ch1b = (const float*)d_in[4];
  P.ch2w = (const float*)d_in[5];  P.ch2b = (const float*)d_in[6];
  P.tk1w = (const float*)d_in[7];  P.tk1b = (const float*)d_in[8];
  P.tk2w = (const float*)d_in[9];  P.tk2b = (const float*)d_in[10];
  P.bn1w = (const float*)d_in[11]; P.bn1b = (const float*)d_in[12];
  P.bt1w = (const float*)d_in[13]; P.bt1b = (const float*)d_in[14];
  P.bt2w = (const float*)d_in[15]; P.bt2b = (const float*)d_in[16];
  P.bn2w = (const float*)d_in[17]; P.bn2b = (const float*)d_in[18];
  P.bc1w = (const float*)d_in[19]; P.bc1b = (const float*)d_in[20];
  P.bc2w = (const float*)d_in[21]; P.bc2b = (const float*)d_in[22];
  P.nw   = (const float*)d_in[23]; P.nb   = (const float*)d_in[24];
  P.e1w  = (const float*)d_in[25]; P.e1b  = (const float*)d_in[26];
  P.e2w  = (const float*)d_in[27]; P.e2b  = (const float*)d_in[28];

  const int NRows = 8192;
  float* ob = (float*)d_out;
  P.out      = ob;
  P.mask_out = ob + (size_t)NRows*NH;
  P.pos_out  = ob + (size_t)NRows*NH + NRows;

  cudaFuncSetAttribute(lane_fusion_kernel,
                       cudaFuncAttributeMaxDynamicSharedMemorySize, SMEM_BYTES);
  lane_fusion_kernel<<<NRows, 256, SMEM_BYTES>>>(P);
}

// round 13
// speedup vs baseline: 2.0381x; 1.2391x over previous
#include <cuda_runtime.h>
#include <math.h>
#include <stdint.h>

#define NV 20
#define NC 128
#define NT 64
#define NH 192
#define N_TL 9
#define N_LT 20
#define NDEPTH 3

#define PA  136   // activation pitch (floats): conflict-free mma fragments
#define PWT 68    // transposed token-weight pitch

// shared layout (floats)
#define OFF_SF   0        // f state [64][136]
#define OFF_SY   8704     // scratch  [64][136]
#define OFF_WT0  17408    // token W1 transposed [64][68]
#define OFF_WT1  21760    // token W2 transposed [64][68]
#define OFF_WC0  26112    // chan W tile [32][136]
#define OFF_WC1  30464    // chan W tile [32][136]
#define OFF_SG   34816    // 96
#define OFF_SRED 34912    // 16
#define OFF_SIDX 34928    // 64 ints
#define SMEM_FLOATS 34992
#define SMEM_BYTES (SMEM_FLOATS*4)

struct Params {
  const float* x;
  const float* tl_table; const float* lane_table;
  const float* ch1w; const float* ch1b; const float* ch2w; const float* ch2b;
  const float* tk1w; const float* tk1b; const float* tk2w; const float* tk2b;
  const float* bn1w; const float* bn1b;
  const float* bt1w; const float* bt1b; const float* bt2w; const float* bt2b;
  const float* bn2w; const float* bn2b;
  const float* bc1w; const float* bc1b; const float* bc2w; const float* bc2b;
  const float* nw;  const float* nb;
  const float* e1w; const float* e1b; const float* e2w; const float* e2b;
  float* out; float* mask_out; float* pos_out;
};

__device__ __forceinline__ float gelu_f(float v){
  return 0.5f * v * (1.0f + erff(v * 0.70710678118654752440f));
}
__device__ __forceinline__ uint32_t tf32r(float x){
  uint32_t r; asm("cvt.rna.tf32.f32 %0, %1;" : "=r"(r) : "f"(x)); return r;
}
__device__ __forceinline__ float tf32f(float x){ return __uint_as_float(tf32r(x)); }

__device__ __forceinline__ void mma8(float d[4], uint32_t a0, uint32_t a1,
                                     uint32_t a2, uint32_t a3,
                                     uint32_t b0, uint32_t b1){
  asm volatile("mma.sync.aligned.m16n8k8.row.col.f32.tf32.tf32.f32 "
               "{%0,%1,%2,%3}, {%4,%5,%6,%7}, {%8,%9}, {%0,%1,%2,%3};"
               : "+f"(d[0]), "+f"(d[1]), "+f"(d[2]), "+f"(d[3])
               : "r"(a0), "r"(a1), "r"(a2), "r"(a3), "r"(b0), "r"(b1));
}

__device__ __forceinline__ void zacc(float acc[2][4][4]){
  #pragma unroll
  for (int m = 0; m < 2; m++)
    #pragma unroll
    for (int j = 0; j < 4; j++)
      #pragma unroll
      for (int q = 0; q < 4; q++) acc[m][j][q] = 0.f;
}

// ---- channel-type GEMM, one staged 32-k tile -------------------------------
// out[m][n] = sum_k Act[m][k] * Wc[k][n]; Act [64][PA], Wc tile [32][PA].
__device__ __forceinline__ void chan_tile_mma(const float* Act, const float* Wc,
                                              float acc[2][4][4], int mbase, int nbase,
                                              int k0, int g, int tg, bool active){
  if (!active) return;
  #pragma unroll
  for (int kk = 0; kk < 32; kk += 8){
    uint32_t af[2][4];
    #pragma unroll
    for (int mi = 0; mi < 2; mi++){
      const float* ap = Act + (mbase + mi*16 + g)*PA + k0 + kk + tg;
      af[mi][0] = __float_as_uint(ap[0]);
      af[mi][1] = __float_as_uint(ap[8*PA]);
      af[mi][2] = __float_as_uint(ap[4]);
      af[mi][3] = __float_as_uint(ap[8*PA + 4]);
    }
    const float* bp = Wc + (kk + tg)*PA + nbase + g;
    #pragma unroll
    for (int j = 0; j < 4; j++){
      uint32_t b0 = __float_as_uint(bp[8*j]);
      uint32_t b1 = __float_as_uint(bp[4*PA + 8*j]);
      #pragma unroll
      for (int mi = 0; mi < 2; mi++)
        mma8(acc[mi][j], af[mi][0], af[mi][1], af[mi][2], af[mi][3], b0, b1);
    }
  }
}

// stage one 32x128 weight tile: gmem -> regs -> smem (tf32-rounded)
__device__ __forceinline__ void ldg_wc(float4 pre[4], const float* __restrict__ src, int tid){
  const float4* g4 = reinterpret_cast<const float4*>(src);
  #pragma unroll
  for (int q = 0; q < 4; q++) pre[q] = g4[tid + 256*q];
}
__device__ __forceinline__ void sts_wc(const float4 pre[4], float* wc, int tid){
  #pragma unroll
  for (int q = 0; q < 4; q++){
    int idx = tid + 256*q;
    int row = idx >> 5;
    int col = (idx & 31) * 4;
    float4 v;
    v.x = __uint_as_float(tf32r(pre[q].x));
    v.y = __uint_as_float(tf32r(pre[q].y));
    v.z = __uint_as_float(tf32r(pre[q].z));
    v.w = __uint_as_float(tf32r(pre[q].w));
    *reinterpret_cast<float4*>(wc + row*PA + col) = v;
  }
}

// full K=128 chan GEMM; precondition: tile0 in wc0 + synced.
// postcondition: if WgNext, its tile0 sits in wc0 (synced).
__device__ void chan_gemm(const float* Act, const float* __restrict__ Wg,
                          const float* __restrict__ WgNext,
                          float acc[2][4][4], float* wc0, float* wc1,
                          int mbase, int nbase, int g, int tg, int tid, bool active){
  float4 pre[4];
  #pragma unroll
  for (int t = 0; t < 4; t++){
    const float* nsrc = (t < 3) ? (Wg + (t+1)*32*NC) : WgNext;
    if (nsrc) ldg_wc(pre, nsrc, tid);
    chan_tile_mma(Act, (t & 1) ? wc1 : wc0, acc, mbase, nbase, t*32, g, tg, active);
    if (nsrc) sts_wc(pre, (t & 1) ? wc0 : wc1, tid);
    __syncthreads();
  }
}

// ---- token-type GEMM: out[u][c] = sum_t wT[u][t] * Act[t][c] ---------------
template<int K8>
__device__ __forceinline__ void tok_mma(const float* Act, const float* wT,
                                        float acc[2][4][4], int mbase, int nbase,
                                        int g, int tg){
  #pragma unroll
  for (int ks = 0; ks < K8; ks++){
    uint32_t af[2][4];
    #pragma unroll
    for (int mi = 0; mi < 2; mi++){
      const float* ap = wT + (mbase + mi*16 + g)*PWT + 8*ks + tg;
      af[mi][0] = __float_as_uint(ap[0]);
      af[mi][1] = __float_as_uint(ap[8*PWT]);
      af[mi][2] = __float_as_uint(ap[4]);
      af[mi][3] = __float_as_uint(ap[8*PWT + 4]);
    }
    const float* bp = Act + (8*ks + tg)*PA + nbase + g;
    #pragma unroll
    for (int j = 0; j < 4; j++){
      uint32_t b0 = __float_as_uint(bp[8*j]);
      uint32_t b1 = __float_as_uint(bp[4*PA + 8*j]);
      #pragma unroll
      for (int mi = 0; mi < 2; mi++)
        mma8(acc[mi][j], af[mi][0], af[mi][1], af[mi][2], af[mi][3], b0, b1);
    }
  }
}

// stage token weight transposed + rounded: g[Krows][64] -> wT[64][PWT] (cols >= Krows zero)
__device__ void stage_wt(float* wT, const float* __restrict__ gsrc,
                         int Krows, int Kpad, int tid){
  for (int idx = tid; idx < Kpad*64; idx += 256){
    int t = idx >> 6, u = idx & 63;
    float v = (t < Krows) ? gsrc[idx] : 0.f;
    wT[u*PWT + t] = __uint_as_float(tf32r(v));
  }
}

// LN of one row; rounded (tf32) store — output feeds mma operands
__device__ __forceinline__ void ln_row(const float* srow, float* drow,
                                       const float wg[4], const float bg[4], int lane){
  float v[4]; float s = 0.f, q = 0.f;
  #pragma unroll
  for (int j = 0; j < 4; j++){
    v[j] = srow[lane + 32*j];
    s += v[j]; q += v[j]*v[j];
  }
  #pragma unroll
  for (int o = 16; o > 0; o >>= 1){
    s += __shfl_xor_sync(0xffffffffu, s, o);
    q += __shfl_xor_sync(0xffffffffu, q, o);
  }
  float m   = s * (1.f/NC);
  float var = q * (1.f/NC) - m*m;
  float rs  = rsqrtf(var + 1e-5f);
  #pragma unroll
  for (int j = 0; j < 4; j++)
    drow[lane + 32*j] = tf32f((v[j]-m)*rs*wg[j] + bg[j]);
}

__global__ void __launch_bounds__(256)
lane_fusion_kernel(Params P){
  extern __shared__ float smem[];
  float* sf  = smem + OFF_SF;
  float* sy  = smem + OFF_SY;
  float* wt0 = smem + OFF_WT0;
  float* wt1 = smem + OFF_WT1;
  float* wc0 = smem + OFF_WC0;
  float* wc1 = smem + OFF_WC1;
  float* sg  = smem + OFF_SG;
  float* sred= smem + OFF_SRED;
  int*   sidx= (int*)(smem + OFF_SIDX);

  const int tid  = threadIdx.x;
  const int lane = tid & 31;
  const int warp = tid >> 5;
  const int g_   = lane >> 2;     // mma group id
  const int tg   = lane & 3;      // thread in group
  const int mbase = (warp & 1) * 32;   // warp m-range (2 m-tiles)
  const int nbase = (warp >> 1) * 32;  // warp n-range (4 n8-tiles)
  const int r    = blockIdx.x;
  const float* xr = P.x + (size_t)r * (NV*5);

  // ----- preprocess -----
  if (tid < NV){
    float x0 = xr[tid*5+0], x1 = xr[tid*5+1], hg = xr[tid*5+2];
    float x3 = xr[tid*5+3], x4 = xr[tid*5+4];
    float ch = cosf(hg), sh = sinf(hg);
    sg[tid*4+0] = x0; sg[tid*4+1] = x1; sg[tid*4+2] = ch; sg[tid*4+3] = sh;
    int tl = (int)x3; tl = tl < 0 ? 0 : (tl > N_TL-1 ? N_TL-1 : tl);
    int lt = (int)x4; lt = lt < 0 ? 0 : (lt > N_LT-1 ? N_LT-1 : lt);
    sidx[tid]      = tl;
    sidx[NV+tid]   = lt;
    sidx[2*NV+tid] = (x0==0.f && x1==0.f && ch==0.f && sh==0.f) ? 1 : 0;
  }
  if (tid < 5){
    float mid = xr[(NV/2)*5 + tid];
    float sc = (tid==3) ? (1.f/(N_TL-1)) : ((tid==4) ? (1.f/(N_LT-1)) : 1.f);
    P.pos_out[(size_t)r*5 + tid] = mid * sc;
  }
  __syncthreads();
  if (tid == 0){
    int mp = 1;
    for (int v = 0; v < NV; v++) mp &= sidx[2*NV+v];
    sidx[3*NV] = mp;
    P.mask_out[r] = mp ? 1.f : 0.f;
  }

  // ----- stage 1a: h1 = gelu(g @ ch1w + b) -> sy rows 0..19 (20..23 zero), tf32
  {
    int c  = tid & 127;
    int hf = tid >> 7;
    float w0 = P.ch1w[0*NC + c], w1 = P.ch1w[1*NC + c];
    float w2 = P.ch1w[2*NC + c], w3 = P.ch1w[3*NC + c];
    float b  = P.ch1b[c];
    #pragma unroll
    for (int v = hf*10; v < hf*10 + 10; v++){
      float a = b + sg[v*4+0]*w0 + sg[v*4+1]*w1 + sg[v*4+2]*w2 + sg[v*4+3]*w3;
      sy[v*PA + c] = tf32f(gelu_f(a));
    }
    if (hf == 0){
      #pragma unroll
      for (int v = NV; v < 24; v++) sy[v*PA + c] = 0.f;
    }
  }
  // stage token-expansion weights + first ch2w tile
  stage_wt(wt0, P.tk1w, NV, 24, tid);
  stage_wt(wt1, P.tk2w, NT, NT, tid);
  {
    float4 pre[4];
    ldg_wc(pre, P.ch2w, tid);
    sts_wc(pre, wc0, tid);
  }
  __syncthreads();

  // ----- stage 1b: f0 = h1 @ ch2w + b + tables -> sf rows 0..19 (20..23 zero)
  {
    float acc[2][4][4]; zacc(acc);
    bool active = (mbase == 0);   // rows 0..31 only
    chan_gemm(sy, P.ch2w, nullptr, acc, wc0, wc1, 0, nbase, g_, tg, tid, active);
    if (active){
      #pragma unroll
      for (int mi = 0; mi < 2; mi++){
        #pragma unroll
        for (int rr = 0; rr < 2; rr++){
          int v = mi*16 + g_ + rr*8;
          if (v < NV){
            int tl = sidx[v], lt = sidx[NV+v];
            #pragma unroll
            for (int j = 0; j < 4; j++){
              int cn = nbase + 8*j + 2*tg;
              float2 b2 = *reinterpret_cast<const float2*>(P.ch2b + cn);
              float2 t2 = *reinterpret_cast<const float2*>(P.tl_table + tl*NC + cn);
              float2 l2 = *reinterpret_cast<const float2*>(P.lane_table + lt*NC + cn);
              float2 o;
              o.x = tf32f(acc[mi][j][rr*2+0] + b2.x + t2.x + l2.x);
              o.y = tf32f(acc[mi][j][rr*2+1] + b2.y + t2.y + l2.y);
              *reinterpret_cast<float2*>(sf + v*PA + cn) = o;
            }
          } else if (v < 24){
            #pragma unroll
            for (int j = 0; j < 4; j++){
              int cn = nbase + 8*j + 2*tg;
              float2 z; z.x = 0.f; z.y = 0.f;
              *reinterpret_cast<float2*>(sf + v*PA + cn) = z;
            }
          }
        }
      }
    }
  }
  __syncthreads();   // S1: f0 ready

  // ----- token expansion: 20 -> 64 -----
  {
    float acc[2][4][4]; zacc(acc);
    tok_mma<3>(sf, wt0, acc, mbase, nbase, g_, tg);     // B = sf rows 0..23
    // z1 epilogue -> sy (tf32): no race (sy only read before prior sync)
    #pragma unroll
    for (int mi = 0; mi < 2; mi++)
      #pragma unroll
      for (int rr = 0; rr < 2; rr++){
        int u = mbase + mi*16 + g_ + rr*8;
        float bb = P.tk1b[u];
        #pragma unroll
        for (int j = 0; j < 4; j++){
          int cn = nbase + 8*j + 2*tg;
          float2 o;
          o.x = tf32f(gelu_f(acc[mi][j][rr*2+0] + bb));
          o.y = tf32f(gelu_f(acc[mi][j][rr*2+1] + bb));
          *reinterpret_cast<float2*>(sy + u*PA + cn) = o;
        }
      }
  }
  __syncthreads();   // S2: z1 ready, all sf reads done
  {
    float acc[2][4][4]; zacc(acc);
    tok_mma<8>(sy, wt1, acc, mbase, nbase, g_, tg);
    #pragma unroll
    for (int mi = 0; mi < 2; mi++)
      #pragma unroll
      for (int rr = 0; rr < 2; rr++){
        int t = mbase + mi*16 + g_ + rr*8;
        float bb = P.tk2b[t];
        #pragma unroll
        for (int j = 0; j < 4; j++){
          int cn = nbase + 8*j + 2*tg;
          float2 o;
          o.x = acc[mi][j][rr*2+0] + bb;
          o.y = acc[mi][j][rr*2+1] + bb;
          *reinterpret_cast<float2*>(sf + t*PA + cn) = o;   // fp32 state
        }
      }
  }
  __syncthreads();   // S3: f ready

  // ----- mixer blocks -----
  for (int d = 0; d < NDEPTH; d++){
    // LN1 (8 rows/warp) -> sy ; stage this depth's token weights
    {
      float wg[4], bg[4];
      #pragma unroll
      for (int j = 0; j < 4; j++){
        wg[j] = P.bn1w[d*NC + lane + 32*j];
        bg[j] = P.bn1b[d*NC + lane + 32*j];
      }
      #pragma unroll
      for (int i = 0; i < 8; i++){
        int t = warp*8 + i;
        ln_row(sf + t*PA, sy + t*PA, wg, bg, lane);
      }
      stage_wt(wt0, P.bt1w + d*NT*NT, NT, NT, tid);
      stage_wt(wt1, P.bt2w + d*NT*NT, NT, NT, tid);
    }
    __syncthreads();   // A

    // token mix 1
    {
      float acc[2][4][4]; zacc(acc);
      tok_mma<8>(sy, wt0, acc, mbase, nbase, g_, tg);
      __syncthreads(); // B: all y reads done before z overwrite
      #pragma unroll
      for (int mi = 0; mi < 2; mi++)
        #pragma unroll
        for (int rr = 0; rr < 2; rr++){
          int u = mbase + mi*16 + g_ + rr*8;
          float bb = P.bt1b[d*NT + u];
          #pragma unroll
          for (int j = 0; j < 4; j++){
            int cn = nbase + 8*j + 2*tg;
            float2 o;
            o.x = tf32f(gelu_f(acc[mi][j][rr*2+0] + bb));
            o.y = tf32f(gelu_f(acc[mi][j][rr*2+1] + bb));
            *reinterpret_cast<float2*>(sy + u*PA + cn) = o;
          }
        }
    }
    __syncthreads();   // C: z ready

    // token mix 2 + residual
    {
      float acc[2][4][4]; zacc(acc);
      tok_mma<8>(sy, wt1, acc, mbase, nbase, g_, tg);
      #pragma unroll
      for (int mi = 0; mi < 2; mi++)
        #pragma unroll
        for (int rr = 0; rr < 2; rr++){
          int t = mbase + mi*16 + g_ + rr*8;
          float bb = P.bt2b[d*NT + t];
          #pragma unroll
          for (int j = 0; j < 4; j++){
            int cn = nbase + 8*j + 2*tg;
            float2 o = *reinterpret_cast<float2*>(sf + t*PA + cn);
            o.x += acc[mi][j][rr*2+0] + bb;
            o.y += acc[mi][j][rr*2+1] + bb;
            *reinterpret_cast<float2*>(sf + t*PA + cn) = o;
          }
        }
    }
    __syncthreads();   // D: all z reads done; sf updated

    // LN2 -> sy ; stage bc1w tile0 -> wc0
    {
      float wg[4], bg[4];
      #pragma unroll
      for (int j = 0; j < 4; j++){
        wg[j] = P.bn2w[d*NC + lane + 32*j];
        bg[j] = P.bn2b[d*NC + lane + 32*j];
      }
      #pragma unroll
      for (int i = 0; i < 8; i++){
        int t = warp*8 + i;
        ln_row(sf + t*PA, sy + t*PA, wg, bg, lane);
      }
      float4 pre[4];
      ldg_wc(pre, P.bc1w + d*NC*NC, tid);
      sts_wc(pre, wc0, tid);
    }
    __syncthreads();   // E

    // channel mix C1: h = gelu(y2 @ Wc1 + b1) -> sy (tf32)
    {
      float acc[2][4][4]; zacc(acc);
      chan_gemm(sy, P.bc1w + d*NC*NC, P.bc2w + d*NC*NC, acc, wc0, wc1,
                mbase, nbase, g_, tg, tid, true);
      // final internal sync => all C1 reads of sy complete
      #pragma unroll
      for (int j = 0; j < 4; j++){
        int cn = nbase + 8*j + 2*tg;
        float2 b2 = *reinterpret_cast<const float2*>(P.bc1b + d*NC + cn);
        #pragma unroll
        for (int mi = 0; mi < 2; mi++)
          #pragma unroll
          for (int rr = 0; rr < 2; rr++){
            int t = mbase + mi*16 + g_ + rr*8;
            float2 o;
            o.x = tf32f(gelu_f(acc[mi][j][rr*2+0] + b2.x));
            o.y = tf32f(gelu_f(acc[mi][j][rr*2+1] + b2.y));
            *reinterpret_cast<float2*>(sy + t*PA + cn) = o;
          }
      }
    }
    __syncthreads();   // G: h ready

    // channel mix C2: f += h @ Wc2 + b2
    {
      float acc[2][4][4]; zacc(acc);
      chan_gemm(sy, P.bc2w + d*NC*NC, nullptr, acc, wc0, wc1,
                mbase, nbase, g_, tg, tid, true);
      #pragma unroll
      for (int j = 0; j < 4; j++){
        int cn = nbase + 8*j + 2*tg;
        float2 b2 = *reinterpret_cast<const float2*>(P.bc2b + d*NC + cn);
        #pragma unroll
        for (int mi = 0; mi < 2; mi++)
          #pragma unroll
          for (int rr = 0; rr < 2; rr++){
            int t = mbase + mi*16 + g_ + rr*8;
            float2 o = *reinterpret_cast<float2*>(sf + t*PA + cn);
            o.x += acc[mi][j][rr*2+0] + b2.x;
            o.y += acc[mi][j][rr*2+1] + b2.y;
            *reinterpret_cast<float2*>(sf + t*PA + cn) = o;
          }
      }
    }
    __syncthreads();   // H: sf complete for next LN1 / epilogue
  }

  // ----- epilogue: token mean, LN, emb MLP (scalar fp32) -----
  {
    int c  = tid & 127;
    int hf = tid >> 7;
    float ps = 0.f;
    #pragma unroll 8
    for (int t = hf*32; t < hf*32 + 32; t++) ps += sf[t*PA + c];
    sy[hf*128 + c] = ps;
  }
  __syncthreads();
  float fm = 0.f;
  if (tid < NC){
    fm = (sy[tid] + sy[128 + tid]) * (1.f/NT);
    float s = fm, q = fm*fm;
    #pragma unroll
    for (int o = 16; o > 0; o >>= 1){
      s += __shfl_xor_sync(0xffffffffu, s, o);
      q += __shfl_xor_sync(0xffffffffu, q, o);
    }
    if (lane == 0){ sred[warp] = s; sred[4+warp] = q; }
  }
  __syncthreads();
  if (tid < NC){
    float s = sred[0]+sred[1]+sred[2]+sred[3];
    float q = sred[4]+sred[5]+sred[6]+sred[7];
    float m  = s * (1.f/NC);
    float var = q * (1.f/NC) - m*m;
    float rs = rsqrtf(var + 1e-5f);
    sy[256 + tid] = (fm - m)*rs*P.nw[tid] + P.nb[tid];
  }
  __syncthreads();
  if (tid < NH){
    float a = P.e1b[tid];
    #pragma unroll 8
    for (int c = 0; c < NC; c++) a += sy[256 + c] * P.e1w[c*NH + tid];
    sy[512 + tid] = gelu_f(a);
  }
  __syncthreads();
  if (tid < NH){
    float o = P.e2b[tid];
    #pragma unroll 8
    for (int j = 0; j < NH; j++) o += sy[512 + j] * P.e2w[j*NH + tid];
    float valid = sidx[3*NV] ? 0.f : 1.f;
    P.out[(size_t)r * NH + tid] = o * valid;
  }
}

extern "C" void kernel_launch(void* const* d_in, const int* in_sizes, int n_in,
                              void* d_out, int out_size){
  (void)in_sizes; (void)n_in; (void)out_size;
  Params P;
  P.x         = (const float*)d_in[0];
  P.tl_table  = (const float*)d_in[1];
  P.lane_table= (const float*)d_in[2];
  P.ch1w = (const float*)d_in[3];  P.ch1b = (const float*)d_in[4];
  P.ch2w = (const float*)d_in[5];  P.ch2b = (const float*)d_in[6];
  P.tk1w = (const float*)d_in[7];  P.tk1b = (const float*)d_in[8];
  P.tk2w = (const float*)d_in[9];  P.tk2b = (const float*)d_in[10];
  P.bn1w = (const float*)d_in[11]; P.bn1b = (const float*)d_in[12];
  P.bt1w = (const float*)d_in[13]; P.bt1b = (const float*)d_in[14];
  P.bt2w = (const float*)d_in[15]; P.bt2b = (const float*)d_in[16];
  P.bn2w = (const float*)d_in[17]; P.bn2b = (const float*)d_in[18];
  P.bc1w = (const float*)d_in[19]; P.bc1b = (const float*)d_in[20];
  P.bc2w = (const float*)d_in[21]; P.bc2b = (const float*)d_in[22];
  P.nw   = (const float*)d_in[23]; P.nb   = (const float*)d_in[24];
  P.e1w  = (const float*)d_in[25]; P.e1b  = (const float*)d_in[26];
  P.e2w  = (const float*)d_in[27]; P.e2b  = (const float*)d_in[28];

  const int NRows = 8192;
  float* ob = (float*)d_out;
  P.out      = ob;
  P.mask_out = ob + (size_t)NRows*NH;
  P.pos_out  = ob + (size_t)NRows*NH + NRows;

  cudaFuncSetAttribute(lane_fusion_kernel,
                       cudaFuncAttributeMaxDynamicSharedMemorySize, SMEM_BYTES);
  lane_fusion_kernel<<<NRows, 256, SMEM_BYTES>>>(P);
}

// round 14
// speedup vs baseline: 2.8662x; 1.4063x over previous
#include <cuda_runtime.h>
#include <math.h>
#include <stdint.h>

#define NV 20
#define NC 128
#define NT 64
#define NH 192
#define N_TL 9
#define N_LT 20
#define NDEPTH 3

#define PA  136   // activation pitch (floats): conflict-free mma fragments
#define PWT 68    // transposed token-weight pitch

// shared layout (floats) — wt* and wc* share one union region (disjoint in time)
#define OFF_SF   0        // f state [64][136]
#define OFF_SY   8704     // scratch  [64][136]
#define OFF_WU   17408    // union: {wt0[64][68], wt1[64][68]} OR {wc0[32][136], wc1[32][136]}
#define OFF_SG   26112    // 96
#define OFF_SRED 26208    // 16
#define OFF_SIDX 26224    // 64 ints
#define SMEM_FLOATS 26288
#define SMEM_BYTES (SMEM_FLOATS*4)

struct Params {
  const float* x;
  const float* tl_table; const float* lane_table;
  const float* ch1w; const float* ch1b; const float* ch2w; const float* ch2b;
  const float* tk1w; const float* tk1b; const float* tk2w; const float* tk2b;
  const float* bn1w; const float* bn1b;
  const float* bt1w; const float* bt1b; const float* bt2w; const float* bt2b;
  const float* bn2w; const float* bn2b;
  const float* bc1w; const float* bc1b; const float* bc2w; const float* bc2b;
  const float* nw;  const float* nb;
  const float* e1w; const float* e1b; const float* e2w; const float* e2b;
  float* out; float* mask_out; float* pos_out;
};

__device__ __forceinline__ float gelu_f(float v){
  return 0.5f * v * (1.0f + erff(v * 0.70710678118654752440f));
}
__device__ __forceinline__ uint32_t tf32r(float x){
  uint32_t r; asm("cvt.rna.tf32.f32 %0, %1;" : "=r"(r) : "f"(x)); return r;
}
__device__ __forceinline__ float tf32f(float x){ return __uint_as_float(tf32r(x)); }

__device__ __forceinline__ void mma8(float d[4], uint32_t a0, uint32_t a1,
                                     uint32_t a2, uint32_t a3,
                                     uint32_t b0, uint32_t b1){
  asm volatile("mma.sync.aligned.m16n8k8.row.col.f32.tf32.tf32.f32 "
               "{%0,%1,%2,%3}, {%4,%5,%6,%7}, {%8,%9}, {%0,%1,%2,%3};"
               : "+f"(d[0]), "+f"(d[1]), "+f"(d[2]), "+f"(d[3])
               : "r"(a0), "r"(a1), "r"(a2), "r"(a3), "r"(b0), "r"(b1));
}

__device__ __forceinline__ void zacc(float acc[2][4][4]){
  #pragma unroll
  for (int m = 0; m < 2; m++)
    #pragma unroll
    for (int j = 0; j < 4; j++)
      #pragma unroll
      for (int q = 0; q < 4; q++) acc[m][j][q] = 0.f;
}

// ---- channel-type GEMM, one staged 32-k tile -------------------------------
__device__ __forceinline__ void chan_tile_mma(const float* Act, const float* Wc,
                                              float acc[2][4][4], int mbase, int nbase,
                                              int k0, int g, int tg, bool active){
  if (!active) return;
  #pragma unroll
  for (int kk = 0; kk < 32; kk += 8){
    uint32_t af[2][4];
    #pragma unroll
    for (int mi = 0; mi < 2; mi++){
      const float* ap = Act + (mbase + mi*16 + g)*PA + k0 + kk + tg;
      af[mi][0] = __float_as_uint(ap[0]);
      af[mi][1] = __float_as_uint(ap[8*PA]);
      af[mi][2] = __float_as_uint(ap[4]);
      af[mi][3] = __float_as_uint(ap[8*PA + 4]);
    }
    const float* bp = Wc + (kk + tg)*PA + nbase + g;
    #pragma unroll
    for (int j = 0; j < 4; j++){
      uint32_t b0 = __float_as_uint(bp[8*j]);
      uint32_t b1 = __float_as_uint(bp[4*PA + 8*j]);
      #pragma unroll
      for (int mi = 0; mi < 2; mi++)
        mma8(acc[mi][j], af[mi][0], af[mi][1], af[mi][2], af[mi][3], b0, b1);
    }
  }
}

// stage one 32x128 weight tile: gmem -> regs -> smem (tf32-rounded)
__device__ __forceinline__ void ldg_wc(float4 pre[4], const float* __restrict__ src, int tid){
  const float4* g4 = reinterpret_cast<const float4*>(src);
  #pragma unroll
  for (int q = 0; q < 4; q++) pre[q] = g4[tid + 256*q];
}
__device__ __forceinline__ void sts_wc(const float4 pre[4], float* wc, int tid){
  #pragma unroll
  for (int q = 0; q < 4; q++){
    int idx = tid + 256*q;
    int row = idx >> 5;
    int col = (idx & 31) * 4;
    float4 v;
    v.x = __uint_as_float(tf32r(pre[q].x));
    v.y = __uint_as_float(tf32r(pre[q].y));
    v.z = __uint_as_float(tf32r(pre[q].z));
    v.w = __uint_as_float(tf32r(pre[q].w));
    *reinterpret_cast<float4*>(wc + row*PA + col) = v;
  }
}

// full K=128 chan GEMM; precondition: tile0 in wc0 + synced.
// postcondition: if WgNext, its tile0 sits in wc0 (synced).
__device__ void chan_gemm(const float* Act, const float* __restrict__ Wg,
                          const float* __restrict__ WgNext,
                          float acc[2][4][4], float* wc0, float* wc1,
                          int mbase, int nbase, int g, int tg, int tid, bool active){
  float4 pre[4];
  #pragma unroll
  for (int t = 0; t < 4; t++){
    const float* nsrc = (t < 3) ? (Wg + (t+1)*32*NC) : WgNext;
    if (nsrc) ldg_wc(pre, nsrc, tid);
    chan_tile_mma(Act, (t & 1) ? wc1 : wc0, acc, mbase, nbase, t*32, g, tg, active);
    if (nsrc) sts_wc(pre, (t & 1) ? wc0 : wc1, tid);
    __syncthreads();
  }
}

// ---- token-type GEMM: out[u][c] = sum_t wT[u][t] * Act[t][c] ---------------
template<int K8>
__device__ __forceinline__ void tok_mma(const float* Act, const float* wT,
                                        float acc[2][4][4], int mbase, int nbase,
                                        int g, int tg){
  #pragma unroll
  for (int ks = 0; ks < K8; ks++){
    uint32_t af[2][4];
    #pragma unroll
    for (int mi = 0; mi < 2; mi++){
      const float* ap = wT + (mbase + mi*16 + g)*PWT + 8*ks + tg;
      af[mi][0] = __float_as_uint(ap[0]);
      af[mi][1] = __float_as_uint(ap[8*PWT]);
      af[mi][2] = __float_as_uint(ap[4]);
      af[mi][3] = __float_as_uint(ap[8*PWT + 4]);
    }
    const float* bp = Act + (8*ks + tg)*PA + nbase + g;
    #pragma unroll
    for (int j = 0; j < 4; j++){
      uint32_t b0 = __float_as_uint(bp[8*j]);
      uint32_t b1 = __float_as_uint(bp[4*PA + 8*j]);
      #pragma unroll
      for (int mi = 0; mi < 2; mi++)
        mma8(acc[mi][j], af[mi][0], af[mi][1], af[mi][2], af[mi][3], b0, b1);
    }
  }
}

// stage token weight transposed + rounded: g[Krows][64] -> wT[64][PWT]
__device__ void stage_wt(float* wT, const float* __restrict__ gsrc,
                         int Krows, int Kpad, int tid){
  for (int idx = tid; idx < Kpad*64; idx += 256){
    int t = idx >> 6, u = idx & 63;
    float v = (t < Krows) ? gsrc[idx] : 0.f;
    wT[u*PWT + t] = __uint_as_float(tf32r(v));
  }
}

// LN of one row; rounded (tf32) store — output feeds mma operands
__device__ __forceinline__ void ln_row(const float* srow, float* drow,
                                       const float wg[4], const float bg[4], int lane){
  float v[4]; float s = 0.f, q = 0.f;
  #pragma unroll
  for (int j = 0; j < 4; j++){
    v[j] = srow[lane + 32*j];
    s += v[j]; q += v[j]*v[j];
  }
  #pragma unroll
  for (int o = 16; o > 0; o >>= 1){
    s += __shfl_xor_sync(0xffffffffu, s, o);
    q += __shfl_xor_sync(0xffffffffu, q, o);
  }
  float m   = s * (1.f/NC);
  float var = q * (1.f/NC) - m*m;
  float rs  = rsqrtf(var + 1e-5f);
  #pragma unroll
  for (int j = 0; j < 4; j++)
    drow[lane + 32*j] = tf32f((v[j]-m)*rs*wg[j] + bg[j]);
}

__global__ void __launch_bounds__(256, 2)
lane_fusion_kernel(Params P){
  extern __shared__ float smem[];
  float* sf  = smem + OFF_SF;
  float* sy  = smem + OFF_SY;
  float* wt0 = smem + OFF_WU;            // union region, token phase
  float* wt1 = smem + OFF_WU + 4352;
  float* wc0 = smem + OFF_WU;            // union region, channel phase
  float* wc1 = smem + OFF_WU + 4352;
  float* sg  = smem + OFF_SG;
  float* sred= smem + OFF_SRED;
  int*   sidx= (int*)(smem + OFF_SIDX);

  const int tid  = threadIdx.x;
  const int lane = tid & 31;
  const int warp = tid >> 5;
  const int g_   = lane >> 2;
  const int tg   = lane & 3;
  const int mbase = (warp & 1) * 32;
  const int nbase = (warp >> 1) * 32;
  const int r    = blockIdx.x;
  const float* xr = P.x + (size_t)r * (NV*5);

  // ----- preprocess -----
  if (tid < NV){
    float x0 = xr[tid*5+0], x1 = xr[tid*5+1], hg = xr[tid*5+2];
    float x3 = xr[tid*5+3], x4 = xr[tid*5+4];
    float ch = cosf(hg), sh = sinf(hg);
    sg[tid*4+0] = x0; sg[tid*4+1] = x1; sg[tid*4+2] = ch; sg[tid*4+3] = sh;
    int tl = (int)x3; tl = tl < 0 ? 0 : (tl > N_TL-1 ? N_TL-1 : tl);
    int lt = (int)x4; lt = lt < 0 ? 0 : (lt > N_LT-1 ? N_LT-1 : lt);
    sidx[tid]      = tl;
    sidx[NV+tid]   = lt;
    sidx[2*NV+tid] = (x0==0.f && x1==0.f && ch==0.f && sh==0.f) ? 1 : 0;
  }
  if (tid < 5){
    float mid = xr[(NV/2)*5 + tid];
    float sc = (tid==3) ? (1.f/(N_TL-1)) : ((tid==4) ? (1.f/(N_LT-1)) : 1.f);
    P.pos_out[(size_t)r*5 + tid] = mid * sc;
  }
  __syncthreads();
  if (tid == 0){
    int mp = 1;
    for (int v = 0; v < NV; v++) mp &= sidx[2*NV+v];
    sidx[3*NV] = mp;
    P.mask_out[r] = mp ? 1.f : 0.f;
  }

  // ----- stage 1a: h1 = gelu(g @ ch1w + b) -> sy rows 0..19 (20..23 zero), tf32
  {
    int c  = tid & 127;
    int hf = tid >> 7;
    float w0 = P.ch1w[0*NC + c], w1 = P.ch1w[1*NC + c];
    float w2 = P.ch1w[2*NC + c], w3 = P.ch1w[3*NC + c];
    float b  = P.ch1b[c];
    #pragma unroll
    for (int v = hf*10; v < hf*10 + 10; v++){
      float a = b + sg[v*4+0]*w0 + sg[v*4+1]*w1 + sg[v*4+2]*w2 + sg[v*4+3]*w3;
      sy[v*PA + c] = tf32f(gelu_f(a));
    }
    if (hf == 0){
      #pragma unroll
      for (int v = NV; v < 24; v++) sy[v*PA + c] = 0.f;
    }
  }
  // stage first ch2w tile into wc0 (union region: chan phase)
  {
    float4 pre[4];
    ldg_wc(pre, P.ch2w, tid);
    sts_wc(pre, wc0, tid);
  }
  __syncthreads();

  // ----- stage 1b: f0 = h1 @ ch2w + b + tables -> sf rows 0..19 (20..23 zero)
  {
    float acc[2][4][4]; zacc(acc);
    bool active = (mbase == 0);
    chan_gemm(sy, P.ch2w, nullptr, acc, wc0, wc1, 0, nbase, g_, tg, tid, active);
    if (active){
      #pragma unroll
      for (int mi = 0; mi < 2; mi++){
        #pragma unroll
        for (int rr = 0; rr < 2; rr++){
          int v = mi*16 + g_ + rr*8;
          if (v < NV){
            int tl = sidx[v], lt = sidx[NV+v];
            #pragma unroll
            for (int j = 0; j < 4; j++){
              int cn = nbase + 8*j + 2*tg;
              float2 b2 = *reinterpret_cast<const float2*>(P.ch2b + cn);
              float2 t2 = *reinterpret_cast<const float2*>(P.tl_table + tl*NC + cn);
              float2 l2 = *reinterpret_cast<const float2*>(P.lane_table + lt*NC + cn);
              float2 o;
              o.x = tf32f(acc[mi][j][rr*2+0] + b2.x + t2.x + l2.x);
              o.y = tf32f(acc[mi][j][rr*2+1] + b2.y + t2.y + l2.y);
              *reinterpret_cast<float2*>(sf + v*PA + cn) = o;
            }
          } else if (v < 24){
            #pragma unroll
            for (int j = 0; j < 4; j++){
              int cn = nbase + 8*j + 2*tg;
              float2 z; z.x = 0.f; z.y = 0.f;
              *reinterpret_cast<float2*>(sf + v*PA + cn) = z;
            }
          }
        }
      }
    }
  }
  __syncthreads();   // S1: f0 ready; wc reads done — union region free

  // stage token-expansion weights (union region: token phase)
  stage_wt(wt0, P.tk1w, NV, 24, tid);
  stage_wt(wt1, P.tk2w, NT, NT, tid);
  __syncthreads();   // S1b: wt ready

  // ----- token expansion: 20 -> 64 -----
  {
    float acc[2][4][4]; zacc(acc);
    tok_mma<3>(sf, wt0, acc, mbase, nbase, g_, tg);
    #pragma unroll
    for (int mi = 0; mi < 2; mi++)
      #pragma unroll
      for (int rr = 0; rr < 2; rr++){
        int u = mbase + mi*16 + g_ + rr*8;
        float bb = P.tk1b[u];
        #pragma unroll
        for (int j = 0; j < 4; j++){
          int cn = nbase + 8*j + 2*tg;
          float2 o;
          o.x = tf32f(gelu_f(acc[mi][j][rr*2+0] + bb));
          o.y = tf32f(gelu_f(acc[mi][j][rr*2+1] + bb));
          *reinterpret_cast<float2*>(sy + u*PA + cn) = o;
        }
      }
  }
  __syncthreads();   // S2: z1 ready
  {
    float acc[2][4][4]; zacc(acc);
    tok_mma<8>(sy, wt1, acc, mbase, nbase, g_, tg);
    #pragma unroll
    for (int mi = 0; mi < 2; mi++)
      #pragma unroll
      for (int rr = 0; rr < 2; rr++){
        int t = mbase + mi*16 + g_ + rr*8;
        float bb = P.tk2b[t];
        #pragma unroll
        for (int j = 0; j < 4; j++){
          int cn = nbase + 8*j + 2*tg;
          float2 o;
          o.x = acc[mi][j][rr*2+0] + bb;
          o.y = acc[mi][j][rr*2+1] + bb;
          *reinterpret_cast<float2*>(sf + t*PA + cn) = o;   // fp32 state
        }
      }
  }
  __syncthreads();   // S3: f ready

  // ----- mixer blocks -----
  for (int d = 0; d < NDEPTH; d++){
    // LN1 (8 rows/warp) -> sy ; stage this depth's token weights
    {
      float wg[4], bg[4];
      #pragma unroll
      for (int j = 0; j < 4; j++){
        wg[j] = P.bn1w[d*NC + lane + 32*j];
        bg[j] = P.bn1b[d*NC + lane + 32*j];
      }
      #pragma unroll
      for (int i = 0; i < 8; i++){
        int t = warp*8 + i;
        ln_row(sf + t*PA, sy + t*PA, wg, bg, lane);
      }
      stage_wt(wt0, P.bt1w + d*NT*NT, NT, NT, tid);
      stage_wt(wt1, P.bt2w + d*NT*NT, NT, NT, tid);
    }
    __syncthreads();   // A

    // token mix 1
    {
      float acc[2][4][4]; zacc(acc);
      tok_mma<8>(sy, wt0, acc, mbase, nbase, g_, tg);
      __syncthreads(); // B
      #pragma unroll
      for (int mi = 0; mi < 2; mi++)
        #pragma unroll
        for (int rr = 0; rr < 2; rr++){
          int u = mbase + mi*16 + g_ + rr*8;
          float bb = P.bt1b[d*NT + u];
          #pragma unroll
          for (int j = 0; j < 4; j++){
            int cn = nbase + 8*j + 2*tg;
            float2 o;
            o.x = tf32f(gelu_f(acc[mi][j][rr*2+0] + bb));
            o.y = tf32f(gelu_f(acc[mi][j][rr*2+1] + bb));
            *reinterpret_cast<float2*>(sy + u*PA + cn) = o;
          }
        }
    }
    __syncthreads();   // C

    // token mix 2 + residual
    {
      float acc[2][4][4]; zacc(acc);
      tok_mma<8>(sy, wt1, acc, mbase, nbase, g_, tg);
      #pragma unroll
      for (int mi = 0; mi < 2; mi++)
        #pragma unroll
        for (int rr = 0; rr < 2; rr++){
          int t = mbase + mi*16 + g_ + rr*8;
          float bb = P.bt2b[d*NT + t];
          #pragma unroll
          for (int j = 0; j < 4; j++){
            int cn = nbase + 8*j + 2*tg;
            float2 o = *reinterpret_cast<float2*>(sf + t*PA + cn);
            o.x += acc[mi][j][rr*2+0] + bb;
            o.y += acc[mi][j][rr*2+1] + bb;
            *reinterpret_cast<float2*>(sf + t*PA + cn) = o;
          }
        }
    }
    __syncthreads();   // D: all wt reads done — union region free

    // LN2 -> sy ; stage bc1w tile0 -> wc0 (union region: chan phase)
    {
      float wg[4], bg[4];
      #pragma unroll
      for (int j = 0; j < 4; j++){
        wg[j] = P.bn2w[d*NC + lane + 32*j];
        bg[j] = P.bn2b[d*NC + lane + 32*j];
      }
      #pragma unroll
      for (int i = 0; i < 8; i++){
        int t = warp*8 + i;
        ln_row(sf + t*PA, sy + t*PA, wg, bg, lane);
      }
      float4 pre[4];
      ldg_wc(pre, P.bc1w + d*NC*NC, tid);
      sts_wc(pre, wc0, tid);
    }
    __syncthreads();   // E

    // channel mix C1: h = gelu(y2 @ Wc1 + b1) -> sy (tf32)
    {
      float acc[2][4][4]; zacc(acc);
      chan_gemm(sy, P.bc1w + d*NC*NC, P.bc2w + d*NC*NC, acc, wc0, wc1,
                mbase, nbase, g_, tg, tid, true);
      #pragma unroll
      for (int j = 0; j < 4; j++){
        int cn = nbase + 8*j + 2*tg;
        float2 b2 = *reinterpret_cast<const float2*>(P.bc1b + d*NC + cn);
        #pragma unroll
        for (int mi = 0; mi < 2; mi++)
          #pragma unroll
          for (int rr = 0; rr < 2; rr++){
            int t = mbase + mi*16 + g_ + rr*8;
            float2 o;
            o.x = tf32f(gelu_f(acc[mi][j][rr*2+0] + b2.x));
            o.y = tf32f(gelu_f(acc[mi][j][rr*2+1] + b2.y));
            *reinterpret_cast<float2*>(sy + t*PA + cn) = o;
          }
      }
    }
    __syncthreads();   // G: h ready

    // channel mix C2: f += h @ Wc2 + b2
    {
      float acc[2][4][4]; zacc(acc);
      chan_gemm(sy, P.bc2w + d*NC*NC, nullptr, acc, wc0, wc1,
                mbase, nbase, g_, tg, tid, true);
      #pragma unroll
      for (int j = 0; j < 4; j++){
        int cn = nbase + 8*j + 2*tg;
        float2 b2 = *reinterpret_cast<const float2*>(P.bc2b + d*NC + cn);
        #pragma unroll
        for (int mi = 0; mi < 2; mi++)
          #pragma unroll
          for (int rr = 0; rr < 2; rr++){
            int t = mbase + mi*16 + g_ + rr*8;
            float2 o = *reinterpret_cast<float2*>(sf + t*PA + cn);
            o.x += acc[mi][j][rr*2+0] + b2.x;
            o.y += acc[mi][j][rr*2+1] + b2.y;
            *reinterpret_cast<float2*>(sf + t*PA + cn) = o;
          }
      }
    }
    __syncthreads();   // H: sf complete; union region free for next LN1 stage
  }

  // ----- epilogue: token mean, LN, emb MLP (scalar fp32) -----
  {
    int c  = tid & 127;
    int hf = tid >> 7;
    float ps = 0.f;
    #pragma unroll 8
    for (int t = hf*32; t < hf*32 + 32; t++) ps += sf[t*PA + c];
    sy[hf*128 + c] = ps;
  }
  __syncthreads();
  float fm = 0.f;
  if (tid < NC){
    fm = (sy[tid] + sy[128 + tid]) * (1.f/NT);
    float s = fm, q = fm*fm;
    #pragma unroll
    for (int o = 16; o > 0; o >>= 1){
      s += __shfl_xor_sync(0xffffffffu, s, o);
      q += __shfl_xor_sync(0xffffffffu, q, o);
    }
    if (lane == 0){ sred[warp] = s; sred[4+warp] = q; }
  }
  __syncthreads();
  if (tid < NC){
    float s = sred[0]+sred[1]+sred[2]+sred[3];
    float q = sred[4]+sred[5]+sred[6]+sred[7];
    float m  = s * (1.f/NC);
    float var = q * (1.f/NC) - m*m;
    float rs = rsqrtf(var + 1e-5f);
    sy[256 + tid] = (fm - m)*rs*P.nw[tid] + P.nb[tid];
  }
  __syncthreads();
  if (tid < NH){
    float a = P.e1b[tid];
    #pragma unroll 8
    for (int c = 0; c < NC; c++) a += sy[256 + c] * P.e1w[c*NH + tid];
    sy[512 + tid] = gelu_f(a);
  }
  __syncthreads();
  if (tid < NH){
    float o = P.e2b[tid];
    #pragma unroll 8
    for (int j = 0; j < NH; j++) o += sy[512 + j] * P.e2w[j*NH + tid];
    float valid = sidx[3*NV] ? 0.f : 1.f;
    P.out[(size_t)r * NH + tid] = o * valid;
  }
}

extern "C" void kernel_launch(void* const* d_in, const int* in_sizes, int n_in,
                              void* d_out, int out_size){
  (void)in_sizes; (void)n_in; (void)out_size;
  Params P;
  P.x         = (const float*)d_in[0];
  P.tl_table  = (const float*)d_in[1];
  P.lane_table= (const float*)d_in[2];
  P.ch1w = (const float*)d_in[3];  P.ch1b = (const float*)d_in[4];
  P.ch2w = (const float*)d_in[5];  P.ch2b = (const float*)d_in[6];
  P.tk1w = (const float*)d_in[7];  P.tk1b = (const float*)d_in[8];
  P.tk2w = (const float*)d_in[9];  P.tk2b = (const float*)d_in[10];
  P.bn1w = (const float*)d_in[11]; P.bn1b = (const float*)d_in[12];
  P.bt1w = (const float*)d_in[13]; P.bt1b = (const float*)d_in[14];
  P.bt2w = (const float*)d_in[15]; P.bt2b = (const float*)d_in[16];
  P.bn2w = (const float*)d_in[17]; P.bn2b = (const float*)d_in[18];
  P.bc1w = (const float*)d_in[19]; P.bc1b = (const float*)d_in[20];
  P.bc2w = (const float*)d_in[21]; P.bc2b = (const float*)d_in[22];
  P.nw   = (const float*)d_in[23]; P.nb   = (const float*)d_in[24];
  P.e1w  = (const float*)d_in[25]; P.e1b  = (const float*)d_in[26];
  P.e2w  = (const float*)d_in[27]; P.e2b  = (const float*)d_in[28];

  const int NRows = 8192;
  float* ob = (float*)d_out;
  P.out      = ob;
  P.mask_out = ob + (size_t)NRows*NH;
  P.pos_out  = ob + (size_t)NRows*NH + NRows;

  cudaFuncSetAttribute(lane_fusion_kernel,
                       cudaFuncAttributeMaxDynamicSharedMemorySize, SMEM_BYTES);
  lane_fusion_kernel<<<NRows, 256, SMEM_BYTES>>>(P);
}